// round 1
// baseline (speedup 1.0000x reference)
#include <cuda_runtime.h>
#include <cstdint>

#define N_NODES 20000
#define N_EDGES 340000
#define DENSE_STRIDE 64
#define MAXSLOT 63          // slots 0..62 usable; entry 0 = self => 64 entries total

// ----------------------------- device scratch -------------------------------
__device__ unsigned char  g_ncode[N_NODES];
__device__ unsigned char  g_ecode[N_EDGES];
__device__ unsigned short g_dense[N_NODES * DENSE_STRIDE];     // 2.56 MB
__device__ float          g_agg[N_NODES * 128];                // 10.24 MB

__device__ float g_Qt[2048], g_Kt[2048], g_Vt[2048], g_EKt[2048];
__device__ float g_H1[2048], g_T1[2048], g_T2[2048], g_T3[512];
__device__ float g_Ve1[2048], g_Ve2[2048], g_Vs[512];
__device__ float g_L[256], g_Lself[16], g_u[16];

// ----------------------------- helpers --------------------------------------
__device__ __forceinline__ float wredsum(float v) {
#pragma unroll
    for (int o = 16; o; o >>= 1) v += __shfl_xor_sync(0xffffffffu, v, o);
    return v;
}
__device__ __forceinline__ int wredsumi(int v) {
#pragma unroll
    for (int o = 16; o; o >>= 1) v += __shfl_xor_sync(0xffffffffu, v, o);
    return v;
}
__device__ __forceinline__ float wredmax(float v) {
#pragma unroll
    for (int o = 16; o; o >>= 1) v = fmaxf(v, __shfl_xor_sync(0xffffffffu, v, o));
    return v;
}
__device__ __forceinline__ float iscan(float v, int lane) {
#pragma unroll
    for (int d = 1; d < 32; d <<= 1) {
        float t = __shfl_up_sync(0xffffffffu, v, d);
        if (lane >= d) v += t;
    }
    return v;
}

// ------------------------ init: clear dense + codes --------------------------
__global__ void k_init(const int* __restrict__ node_states,
                       const int* __restrict__ edge_states) {
    int i = blockIdx.x * blockDim.x + threadIdx.x;
    if (i < N_NODES * DENSE_STRIDE) g_dense[i] = 0;
    if (i < N_EDGES) {
        int c = edge_states[i * 4 + 0] + 2 * edge_states[i * 4 + 1] +
                4 * edge_states[i * 4 + 2] + 8 * edge_states[i * 4 + 3];
        g_ecode[i] = (unsigned char)c;
    }
    if (i < N_NODES) {
        int c = node_states[i * 4 + 0] + 2 * node_states[i * 4 + 1] +
                4 * node_states[i * 4 + 2] + 8 * node_states[i * 4 + 3];
        g_ncode[i] = (unsigned char)c;
    }
}

// ------------------------ precompute stage 1 ---------------------------------
// 8 blocks of 128 threads. Mini-GEMMs: out[16x128] = A[16x128] @ W[128x128]
__global__ void k_pre1(const float* __restrict__ emb_v, const float* __restrict__ emb_b,
                       const float* __restrict__ emb_e, const float* __restrict__ emb_s,
                       const float* __restrict__ Wq, const float* __restrict__ Wk,
                       const float* __restrict__ Wv, const float* __restrict__ Wek,
                       const float* __restrict__ gW1, const float* __restrict__ gb1,
                       const float* __restrict__ Wcf) {
    __shared__ float As[16 * 128];
    int t = threadIdx.x, b = blockIdx.x;
    const float* W = 0; float* out = 0; int rows = 16;
    const float* bias = 0; bool do_relu = false;
#pragma unroll
    for (int r = 0; r < 16; r++) As[r * 128 + t] = 0.f;
    switch (b) {
        case 0: for (int r = 0; r < 16; r++) As[r*128+t] = emb_v[2*r*128 + t];
                W = Wq;  out = g_Qt;  break;
        case 1: for (int r = 0; r < 16; r++) As[r*128+t] = emb_v[2*r*128 + t];
                W = Wk;  out = g_Kt;  break;
        case 2: for (int r = 0; r < 16; r++) As[r*128+t] = emb_v[2*r*128 + t];
                W = Wv;  out = g_Vt;  break;
        case 3: for (int r = 0; r < 16; r++) As[r*128+t] = emb_b[2*r*128 + t];
                W = Wek; out = g_EKt; break;
        case 4: for (int r = 0; r < 16; r++) As[r*128+t] = emb_v[2*r*128 + t];
                W = gW1; out = g_H1; bias = gb1; do_relu = true; break;
        case 5: for (int r = 0; r < 16; r++) As[r*128+t] = emb_e[r*128 + t];
                W = Wcf;               out = g_T1; break;
        case 6: for (int r = 0; r < 16; r++) As[r*128+t] = emb_e[r*128 + t];
                W = Wcf + 128 * 128;   out = g_T2; break;
        case 7: for (int r = 0; r < 4;  r++) As[r*128+t] = emb_s[r*128 + t];
                W = Wcf + 256 * 128;   out = g_T3; rows = 4; break;
    }
    __syncthreads();
    float acc[16];
#pragma unroll
    for (int r = 0; r < 16; r++) acc[r] = 0.f;
    for (int k = 0; k < 128; k++) {
        float w = W[k * 128 + t];
#pragma unroll
        for (int r = 0; r < 16; r++) acc[r] += As[r * 128 + k] * w;
    }
    for (int r = 0; r < rows; r++) {
        float v = acc[r];
        if (bias) v += bias[t];
        if (do_relu) v = fmaxf(v, 0.f);
        out[r * 128 + t] = v;
    }
}

// ------------------------ precompute stage 2 ---------------------------------
__global__ void k_pre2(const float* __restrict__ Wev,
                       const float* __restrict__ gW2, const float* __restrict__ gb2) {
    __shared__ float As[16 * 128];
    __shared__ float Bs[16 * 128];
    int t = threadIdx.x, b = blockIdx.x;
    if (b < 3) {
        const float* src = (b == 0) ? g_T1 : (b == 1) ? g_T2 : g_T3;
        int rows = (b == 2) ? 4 : 16;
        for (int r = 0; r < 16; r++) As[r * 128 + t] = (r < rows) ? src[r * 128 + t] : 0.f;
        __syncthreads();
        float acc[16];
#pragma unroll
        for (int r = 0; r < 16; r++) acc[r] = 0.f;
        for (int k = 0; k < 128; k++) {
            float w = Wev[k * 128 + t];
#pragma unroll
            for (int r = 0; r < 16; r++) acc[r] += As[r * 128 + k] * w;
        }
        float* out = (b == 0) ? g_Ve1 : (b == 1) ? g_Ve2 : g_Vs;
        for (int r = 0; r < rows; r++) out[r * 128 + t] = acc[r];
    } else {
        // KE = K + EK ; L[qc][sc] = Q[qc].KE[sc]/sqrt(h) ; Lself ; u
        for (int r = 0; r < 16; r++) {
            As[r * 128 + t] = g_Qt[r * 128 + t];
            Bs[r * 128 + t] = g_Kt[r * 128 + t] + g_EKt[r * 128 + t];
        }
        __syncthreads();
        const float SH = 11.31370849898476f;   // sqrt(128)
#pragma unroll
        for (int pi = 0; pi < 2; pi++) {
            int p = t + pi * 128;
            int qc = p >> 4, sc = p & 15;
            float a = 0.f;
            for (int k = 0; k < 128; k++) a += As[qc * 128 + k] * Bs[sc * 128 + k];
            g_L[p] = a / SH;
        }
        if (t < 16) {
            float a = 0.f;
            for (int k = 0; k < 128; k++) a += As[t * 128 + k] * g_Kt[t * 128 + k];
            g_Lself[t] = a / SH;
            float h = 0.f;
            for (int k = 0; k < 128; k++) h += g_H1[t * 128 + k] * gW2[k];
            h += gb2[0];
            g_u[t] = 1.0f / (1.0f + expf(-h));
        }
    }
}

// ------------------------ pack + scatter -------------------------------------
__global__ void k_pack(const int* __restrict__ src, const int* __restrict__ dst,
                       const int* __restrict__ rev, const int* __restrict__ slot,
                       const float* __restrict__ scalars) {
    int e = blockIdx.x * blockDim.x + threadIdx.x;
    if (e >= N_EDGES) return;
    int s_ = src[e], d_ = dst[e];
    int sc = g_ncode[s_];
    int ec = g_ecode[e];
    int rc = g_ecode[rev[e]];
    float sv = scalars[e];
    float rs = scalars[d_];
    float ss = scalars[s_];
    int rlx  = (sv < rs) ? 1 : 0;
    int rlxd = ((ss + sv) < rs) ? 1 : 0;
    int stc = rlx | (rlxd << 1);
    int pk = sc | (ec << 4) | (rc << 8) | (stc << 12) | 0x4000;
    int sl = slot[e];
    if (sl < MAXSLOT) g_dense[d_ * DENSE_STRIDE + sl] = (unsigned short)pk;
}

// ------------------------ main attention kernel ------------------------------
// 512 threads = 16 warps = 16 nodes per block. grid = 1250.
__global__ __launch_bounds__(512) void k_attn(const float* __restrict__ emb_v,
                                              float* __restrict__ out_node) {
    __shared__ float sTab[68 * 128];     // 0..15 V_tab | 16..31 Ve1 | 32..47 Ve2 | 48..51 Vs | 52..67 NF
    __shared__ float sL[256];
    __shared__ float sLs[16];
    __shared__ float sU[16];
    __shared__ float sBA[16][64];
    __shared__ float sBB[16][64];

    int tid = threadIdx.x;
    for (int i = tid; i < 68 * 128; i += 512) {
        int row = i >> 7, col = i & 127;
        float v;
        if      (row < 16) v = g_Vt[i];
        else if (row < 32) v = g_Ve1[(row - 16) * 128 + col];
        else if (row < 48) v = g_Ve2[(row - 32) * 128 + col];
        else if (row < 52) v = g_Vs[(row - 48) * 128 + col];
        else               v = emb_v[(row - 52) * 256 + col];   // emb_v[2*(row-52)]
        sTab[i] = v;
    }
    if (tid < 256) sL[tid] = g_L[tid];
    if (tid < 16) { sLs[tid] = g_Lself[tid]; sU[tid] = g_u[tid]; }
    __syncthreads();

    int warp = tid >> 5, lane = tid & 31;
    int n = blockIdx.x * 16 + warp;
    float* bA = sBA[warp];
    float* bB = sBB[warp];
    int nc = g_ncode[n];

    // ---- gather entries (idx 0 = self; idx i>=1 => dense slot i-1) ----
    int pkA, pkB, actA, actB;
    float vA, vB;
    if (lane == 0) { pkA = 0x8000 | nc; vA = sLs[nc]; actA = 1; }
    else {
        unsigned short pk = g_dense[n * DENSE_STRIDE + lane - 1];
        actA = (pk >> 14) & 1; pkA = pk & 0x3FFF;
        vA = actA ? sL[(nc << 4) | (pkA & 15)] : -1e9f;
    }
    {
        unsigned short pk = g_dense[n * DENSE_STRIDE + lane + 31];
        actB = (pk >> 14) & 1; pkB = pk & 0x3FFF;
        vB = actB ? sL[(nc << 4) | (pkB & 15)] : -1e9f;
    }
    int A = wredsumi(actA + actB);                       // active entry count

    // ---- softmax ----
    float mx = wredmax(fmaxf(vA, vB));
    float eA = expf(vA - mx), eB = expf(vB - mx);        // masked -> exp(-1e9)=0
    float S  = wredsum(eA + eB);
    float psA = eA / S, psB = eB / S;

    // ---- rank-sort (descending, stable by idx) ----
    bA[lane] = vA; bA[lane + 32] = vB;
    __syncwarp();
    int rA = 0, rB = 0;
#pragma unroll 8
    for (int j = 0; j < 64; j++) {
        float vj = bA[j];
        rA += (vj > vA) || (vj == vA && j < lane);
        rB += (vj > vB) || (vj == vB && j < lane + 32);
    }
    __syncwarp();
    bB[rA] = vA; bB[rB] = vB;
    __syncwarp();
    float z0 = bB[lane], z1 = bB[lane + 32];

    // ---- cumsums (cz, cz2) via warp scans ----
    float cz0 = iscan(z0, lane);
    float tot = __shfl_sync(0xffffffffu, cz0, 31);
    float cz1 = iscan(z1, lane) + tot;
    float q0  = iscan(z0 * z0, lane);
    float qt  = __shfl_sync(0xffffffffu, q0, 31);
    float q1  = iscan(z1 * z1, lane) + qt;

    float kAf = (float)(lane + 1), kBf = (float)(lane + 33);
    float mzA = cz0 / kAf, mz2A = q0 / kAf;
    float dA = fmaxf(mzA * mzA - mz2A + 1.0f / kAf, 0.f);
    float tcA = mzA - sqrtf(dA);
    float mzB = cz1 / kBf, mz2B = q1 / kBf;
    float dB = fmaxf(mzB * mzB - mz2B + 1.0f / kBf, 0.f);
    float tcB = mzB - sqrtf(dB);

    int k15 = wredsumi((z0 > tcA) + (z1 > tcB));
    int ksp = wredsumi((kAf * z0 > cz0 - 1.0f) + (kBf * z1 > cz1 - 1.0f));

    __syncwarp();
    bA[lane] = tcA; bA[lane + 32] = tcB;
    bB[lane] = cz0; bB[lane + 32] = cz1;
    __syncwarp();
    float tau15 = bA[k15 - 1];
    float tausp = (bB[ksp - 1] - 1.0f) / (float)ksp;

    // ---- probs, straight-through hard attention ----
    float r0 = fmaxf(vA - tau15, 0.f); float p15A = r0 * r0;
    float r1 = fmaxf(vB - tau15, 0.f); float p15B = r1 * r1;
    float pspA = fmaxf(vA - tausp, 0.f);
    float pspB = fmaxf(vB - tausp, 0.f);
    float uu = sU[nc];
    float prA, prB;
    if (uu <= 0.5f) {
        float w = uu * 2.0f;
        prA = (1.0f - w) * psA + w * p15A;
        prB = (1.0f - w) * psB + w * p15B;
    } else {
        float w = (uu - 0.5f) * 2.0f;
        prA = (1.0f - w) * p15A + w * pspA;
        prB = (1.0f - w) * p15B + w * pspB;
    }
    float selA = (prA > 1e-6f) ? 1.f : 0.f;
    float selB = (prB > 1e-6f) ? 1.f : 0.f;
    float ssum = wredsum(selA + selB) + 1e-9f;
    float attA = ((selA / ssum) - prA) + prA; if (!actA) attA = 0.f;
    float attB = ((selB / ssum) - prB) + prB; if (!actB) attB = 0.f;

    __syncwarp();
    bA[lane] = attA;           bA[lane + 32] = attB;
    bB[lane] = __int_as_float(pkA); bB[lane + 32] = __int_as_float(pkB);
    __syncwarp();

    // ---- aggregate: lane owns columns 4*lane..4*lane+3 ----
    float4 acc = make_float4(0.f, 0.f, 0.f, 0.f);
    const float4* T4 = (const float4*)sTab;
    for (int i = 0; i < A; i++) {
        float a = bA[i];
        if (a != 0.f) {
            int p = __float_as_int(bB[i]);
            float4 t = T4[(p & 15) * 32 + lane];
            acc.x += a * t.x; acc.y += a * t.y; acc.z += a * t.z; acc.w += a * t.w;
            if (!(p & 0x8000)) {
                float4 t1 = T4[(16 + ((p >> 4) & 15)) * 32 + lane];
                float4 t2 = T4[(32 + ((p >> 8) & 15)) * 32 + lane];
                float4 t3 = T4[(48 + ((p >> 12) & 3)) * 32 + lane];
                acc.x += a * (t1.x + t2.x + t3.x);
                acc.y += a * (t1.y + t2.y + t3.y);
                acc.z += a * (t1.z + t2.z + t3.z);
                acc.w += a * (t1.w + t2.w + t3.w);
            }
        }
    }
    float4 nf = T4[(52 + nc) * 32 + lane];
    float4 no = make_float4(acc.x + nf.x, acc.y + nf.y, acc.z + nf.z, acc.w + nf.w);
    ((float4*)g_agg)[n * 32 + lane] = acc;
    ((float4*)out_node)[n * 32 + lane] = no;
}

// ------------------------ edge output ----------------------------------------
__global__ void k_edge(const int* __restrict__ dst, const float* __restrict__ emb_e,
                       float* __restrict__ out_edge) {
    int idx = blockIdx.x * blockDim.x + threadIdx.x;
    int e = idx >> 5, q = idx & 31;
    if (e >= N_EDGES) return;
    int d = __ldg(dst + e);
    int ec = g_ecode[e];
    float4 a  = __ldg(((const float4*)g_agg) + d * 32 + q);
    float4 em = __ldg(((const float4*)emb_e) + ec * 32 + q);
    float4 o = make_float4(em.x + a.x, em.y + a.y, em.z + a.z, em.w + a.w);
    ((float4*)out_edge)[e * 32 + q] = o;
}

// ------------------------ host launch ----------------------------------------
extern "C" void kernel_launch(void* const* d_in, const int* in_sizes, int n_in,
                              void* d_out, int out_size) {
    const int*   node_states = (const int*)d_in[0];
    const int*   edge_states = (const int*)d_in[1];
    const float* scalars     = (const float*)d_in[2];
    const int*   src         = (const int*)d_in[3];
    const int*   dst         = (const int*)d_in[4];
    const int*   rev         = (const int*)d_in[5];
    const int*   slot        = (const int*)d_in[6];
    // d_in[7] = self_loop_idx (identity, unused)

    int w = 8;
    if (w < n_in && in_sizes[w] == 1) w++;   // skip max_deg scalar if present
    const float* emb_v = (const float*)d_in[w + 0];
    const float* emb_b = (const float*)d_in[w + 1];
    const float* emb_e = (const float*)d_in[w + 2];
    const float* emb_s = (const float*)d_in[w + 3];
    const float* Wq    = (const float*)d_in[w + 4];
    const float* Wk    = (const float*)d_in[w + 5];
    const float* Wv    = (const float*)d_in[w + 6];
    const float* Wek   = (const float*)d_in[w + 7];
    const float* Wev   = (const float*)d_in[w + 8];
    const float* Wcf   = (const float*)d_in[w + 9];
    const float* gW1   = (const float*)d_in[w + 10];
    const float* gb1   = (const float*)d_in[w + 11];
    const float* gW2   = (const float*)d_in[w + 12];
    const float* gb2   = (const float*)d_in[w + 13];

    float* out_node = (float*)d_out;
    float* out_edge = (float*)d_out + (size_t)N_NODES * 128;

    k_init<<<(N_NODES * DENSE_STRIDE + 255) / 256, 256>>>(node_states, edge_states);
    k_pre1<<<8, 128>>>(emb_v, emb_b, emb_e, emb_s, Wq, Wk, Wv, Wek, gW1, gb1, Wcf);
    k_pre2<<<4, 128>>>(Wev, gW2, gb2);
    k_pack<<<(N_EDGES + 255) / 256, 256>>>(src, dst, rev, slot, scalars);
    k_attn<<<N_NODES / 16, 512>>>(emb_v, out_node);
    k_edge<<<(N_EDGES * 32) / 256, 256>>>(dst, emb_e, out_edge);
}

// round 2
// speedup vs baseline: 1.5623x; 1.5623x over previous
#include <cuda_runtime.h>
#include <cstdint>

#define N_NODES 20000
#define N_EDGES 340000
#define DENSE_STRIDE 64
#define MAXSLOT 63
#define FULLMASK 0xffffffffu

// ----------------------------- device scratch -------------------------------
__device__ unsigned char  g_ncode[N_NODES];
__device__ unsigned char  g_ecode[N_EDGES];
__device__ unsigned short g_dense[N_NODES * DENSE_STRIDE];     // 2.56 MB
__device__ __align__(16) float g_agg[N_NODES * 128];           // 10.24 MB

__device__ __align__(16) float g_Qt[2048], g_Kt[2048], g_Vt[2048], g_EKt[2048];
__device__ __align__(16) float g_H1[2048], g_T1[2048], g_T2[2048], g_T3[512];
__device__ __align__(16) float g_Ve1[2048], g_Ve2[2048], g_Vs[512];
__device__ float g_L[256], g_Lself[16], g_u[16];

// ----------------------------- helpers --------------------------------------
__device__ __forceinline__ float wredsum(float v) {
#pragma unroll
    for (int o = 16; o; o >>= 1) v += __shfl_xor_sync(FULLMASK, v, o);
    return v;
}
__device__ __forceinline__ int wredsumi(int v) {
#pragma unroll
    for (int o = 16; o; o >>= 1) v += __shfl_xor_sync(FULLMASK, v, o);
    return v;
}
__device__ __forceinline__ float wredmax(float v) {
#pragma unroll
    for (int o = 16; o; o >>= 1) v = fmaxf(v, __shfl_xor_sync(FULLMASK, v, o));
    return v;
}
__device__ __forceinline__ float iscan(float v, int lane) {
#pragma unroll
    for (int d = 1; d < 32; d <<= 1) {
        float t = __shfl_up_sync(FULLMASK, v, d);
        if (lane >= d) v += t;
    }
    return v;
}
// bitonic compare-and-swap on one register across lanes
__device__ __forceinline__ void cas(float& v, bool asc, int j, int lane) {
    float pv = __shfl_xor_sync(FULLMASK, v, j);
    bool keepmin = (((lane & j) == 0) == asc);
    v = keepmin ? fminf(v, pv) : fmaxf(v, pv);
}

// ------------------------ init: clear dense + codes --------------------------
__global__ void k_init(const int* __restrict__ node_states,
                       const int* __restrict__ edge_states) {
    int i = blockIdx.x * blockDim.x + threadIdx.x;
    if (i < N_NODES * DENSE_STRIDE) g_dense[i] = 0;
    if (i < N_EDGES) {
        int c = edge_states[i * 4 + 0] + 2 * edge_states[i * 4 + 1] +
                4 * edge_states[i * 4 + 2] + 8 * edge_states[i * 4 + 3];
        g_ecode[i] = (unsigned char)c;
    }
    if (i < N_NODES) {
        int c = node_states[i * 4 + 0] + 2 * node_states[i * 4 + 1] +
                4 * node_states[i * 4 + 2] + 8 * node_states[i * 4 + 3];
        g_ncode[i] = (unsigned char)c;
    }
}

// ------------------------ precompute stage 1 ---------------------------------
__global__ void k_pre1(const float* __restrict__ emb_v, const float* __restrict__ emb_b,
                       const float* __restrict__ emb_e, const float* __restrict__ emb_s,
                       const float* __restrict__ Wq, const float* __restrict__ Wk,
                       const float* __restrict__ Wv, const float* __restrict__ Wek,
                       const float* __restrict__ gW1, const float* __restrict__ gb1,
                       const float* __restrict__ Wcf) {
    __shared__ float As[16 * 128];
    int t = threadIdx.x, b = blockIdx.x;
    const float* W = 0; float* out = 0; int rows = 16;
    const float* bias = 0; bool do_relu = false;
#pragma unroll
    for (int r = 0; r < 16; r++) As[r * 128 + t] = 0.f;
    switch (b) {
        case 0: for (int r = 0; r < 16; r++) As[r*128+t] = emb_v[2*r*128 + t];
                W = Wq;  out = g_Qt;  break;
        case 1: for (int r = 0; r < 16; r++) As[r*128+t] = emb_v[2*r*128 + t];
                W = Wk;  out = g_Kt;  break;
        case 2: for (int r = 0; r < 16; r++) As[r*128+t] = emb_v[2*r*128 + t];
                W = Wv;  out = g_Vt;  break;
        case 3: for (int r = 0; r < 16; r++) As[r*128+t] = emb_b[2*r*128 + t];
                W = Wek; out = g_EKt; break;
        case 4: for (int r = 0; r < 16; r++) As[r*128+t] = emb_v[2*r*128 + t];
                W = gW1; out = g_H1; bias = gb1; do_relu = true; break;
        case 5: for (int r = 0; r < 16; r++) As[r*128+t] = emb_e[r*128 + t];
                W = Wcf;               out = g_T1; break;
        case 6: for (int r = 0; r < 16; r++) As[r*128+t] = emb_e[r*128 + t];
                W = Wcf + 128 * 128;   out = g_T2; break;
        case 7: for (int r = 0; r < 4;  r++) As[r*128+t] = emb_s[r*128 + t];
                W = Wcf + 256 * 128;   out = g_T3; rows = 4; break;
    }
    __syncthreads();
    float acc[16];
#pragma unroll
    for (int r = 0; r < 16; r++) acc[r] = 0.f;
    for (int k = 0; k < 128; k++) {
        float w = W[k * 128 + t];
#pragma unroll
        for (int r = 0; r < 16; r++) acc[r] += As[r * 128 + k] * w;
    }
    for (int r = 0; r < rows; r++) {
        float v = acc[r];
        if (bias) v += bias[t];
        if (do_relu) v = fmaxf(v, 0.f);
        out[r * 128 + t] = v;
    }
}

// ------------------------ precompute stage 2 ---------------------------------
__global__ void k_pre2(const float* __restrict__ Wev,
                       const float* __restrict__ gW2, const float* __restrict__ gb2) {
    __shared__ float As[16 * 128];
    __shared__ float Bs[16 * 128];
    int t = threadIdx.x, b = blockIdx.x;
    if (b < 3) {
        const float* src = (b == 0) ? g_T1 : (b == 1) ? g_T2 : g_T3;
        int rows = (b == 2) ? 4 : 16;
        for (int r = 0; r < 16; r++) As[r * 128 + t] = (r < rows) ? src[r * 128 + t] : 0.f;
        __syncthreads();
        float acc[16];
#pragma unroll
        for (int r = 0; r < 16; r++) acc[r] = 0.f;
        for (int k = 0; k < 128; k++) {
            float w = Wev[k * 128 + t];
#pragma unroll
            for (int r = 0; r < 16; r++) acc[r] += As[r * 128 + k] * w;
        }
        float* out = (b == 0) ? g_Ve1 : (b == 1) ? g_Ve2 : g_Vs;
        for (int r = 0; r < rows; r++) out[r * 128 + t] = acc[r];
    } else {
        for (int r = 0; r < 16; r++) {
            As[r * 128 + t] = g_Qt[r * 128 + t];
            Bs[r * 128 + t] = g_Kt[r * 128 + t] + g_EKt[r * 128 + t];
        }
        __syncthreads();
        const float SH = 11.31370849898476f;   // sqrt(128)
#pragma unroll
        for (int pi = 0; pi < 2; pi++) {
            int p = t + pi * 128;
            int qc = p >> 4, sc = p & 15;
            float a = 0.f;
            for (int k = 0; k < 128; k++) a += As[qc * 128 + k] * Bs[sc * 128 + k];
            g_L[p] = a / SH;
        }
        if (t < 16) {
            float a = 0.f;
            for (int k = 0; k < 128; k++) a += As[t * 128 + k] * g_Kt[t * 128 + k];
            g_Lself[t] = a / SH;
            float h = 0.f;
            for (int k = 0; k < 128; k++) h += g_H1[t * 128 + k] * gW2[k];
            h += gb2[0];
            g_u[t] = 1.0f / (1.0f + expf(-h));
        }
    }
}

// ------------------------ pack + scatter -------------------------------------
__global__ void k_pack(const int* __restrict__ src, const int* __restrict__ dst,
                       const int* __restrict__ rev, const int* __restrict__ slot,
                       const float* __restrict__ scalars) {
    int e = blockIdx.x * blockDim.x + threadIdx.x;
    if (e >= N_EDGES) return;
    int s_ = __ldg(src + e), d_ = __ldg(dst + e);
    int sc = g_ncode[s_];
    int ec = g_ecode[e];
    int rc = g_ecode[__ldg(rev + e)];
    float sv = __ldg(scalars + e);
    float rs = __ldg(scalars + d_);
    float ss = __ldg(scalars + s_);
    int rlx  = (sv < rs) ? 1 : 0;
    int rlxd = ((ss + sv) < rs) ? 1 : 0;
    int stc = rlx | (rlxd << 1);
    int pk = sc | (ec << 4) | (rc << 8) | (stc << 12) | 0x4000;
    int sl = __ldg(slot + e);
    if (sl < MAXSLOT) g_dense[d_ * DENSE_STRIDE + sl] = (unsigned short)pk;
}

// ------------------------ main attention kernel ------------------------------
// 512 threads = 16 warps = 16 nodes per block. grid = 1250.
__global__ __launch_bounds__(512) void k_attn(const float* __restrict__ emb_v,
                                              float* __restrict__ out_node) {
    __shared__ float sTab[68 * 128];   // 0..15 Vt | 16..31 Ve1 | 32..47 Ve2 | 48..51 Vs | 52..67 NF
    __shared__ float sL[256];
    __shared__ float sLs[16];
    __shared__ float sU[16];

    int tid = threadIdx.x;
    for (int i = tid; i < 68 * 128; i += 512) {
        int row = i >> 7, col = i & 127;
        float v;
        if      (row < 16) v = g_Vt[i];
        else if (row < 32) v = g_Ve1[(row - 16) * 128 + col];
        else if (row < 48) v = g_Ve2[(row - 32) * 128 + col];
        else if (row < 52) v = g_Vs[(row - 48) * 128 + col];
        else               v = emb_v[(row - 52) * 256 + col];   // emb_v[2*(row-52)]
        sTab[i] = v;
    }
    if (tid < 256) sL[tid] = g_L[tid];
    if (tid < 16) { sLs[tid] = g_Lself[tid]; sU[tid] = g_u[tid]; }
    __syncthreads();

    int warp = tid >> 5, lane = tid & 31;
    int n = blockIdx.x * 16 + warp;
    int nc = g_ncode[n];

    // ---- gather entries (idx 0 = self; idx i>=1 => dense slot i-1) ----
    int pkA, pkB, actA, actB;
    float vA, vB;
    if (lane == 0) { pkA = 0x8000 | nc; vA = sLs[nc]; actA = 1; }
    else {
        unsigned short pk = g_dense[n * DENSE_STRIDE + lane - 1];
        actA = (pk >> 14) & 1; pkA = pk & 0x3FFF;
        vA = actA ? sL[(nc << 4) | (pkA & 15)] : -1e9f;
    }
    {
        unsigned short pk = g_dense[n * DENSE_STRIDE + lane + 31];
        actB = (pk >> 14) & 1; pkB = pk & 0x3FFF;
        vB = actB ? sL[(nc << 4) | (pkB & 15)] : -1e9f;
    }
    int A = wredsumi(actA + actB);           // active entry count (>=2)
    float uu = sU[nc];

    float attA = 0.f, attB = 0.f;

    if (A <= 32) {
        // ======== fast path: all real entries live in vA ========
        float mx = wredmax(vA);
        float eA = __expf(vA - mx);
        float S  = wredsum(eA);
        float psA = __fdividef(eA, S);

        // bitonic ascending sort of 32 values, then reverse to descending
        float v = vA;
#pragma unroll
        for (int k = 2; k <= 32; k <<= 1) {
            bool asc = ((lane & k) == 0);
#pragma unroll
            for (int j = k >> 1; j; j >>= 1) cas(v, asc, j, lane);
        }
        float z = __shfl_sync(FULLMASK, v, lane ^ 31);     // descending

        float cz = iscan(z, lane);
        float q  = iscan(z * z, lane);
        float kf = (float)(lane + 1);
        float rk = __fdividef(1.0f, kf);
        float mz = cz * rk, mz2 = q * rk;
        float discr = fmaxf(mz * mz - mz2 + rk, 0.f);
        float tc = mz - sqrtf(discr);

        int k15 = wredsumi(z > tc ? 1 : 0);
        int ksp = wredsumi((kf * z > cz - 1.0f) ? 1 : 0);
        float tau15 = __shfl_sync(FULLMASK, tc, k15 - 1);
        float csk   = __shfl_sync(FULLMASK, cz, ksp - 1);
        float tausp = __fdividef(csk - 1.0f, (float)ksp);

        float r0 = fmaxf(vA - tau15, 0.f); float p15A = r0 * r0;
        float pspA = fmaxf(vA - tausp, 0.f);
        float prA;
        if (uu <= 0.5f) {
            float w = uu * 2.0f;
            prA = (1.0f - w) * psA + w * p15A;
        } else {
            float w = (uu - 0.5f) * 2.0f;
            prA = (1.0f - w) * p15A + w * pspA;
        }
        float selA = (prA > 1e-6f) ? 1.f : 0.f;
        float ssum = wredsum(selA) + 1e-9f;
        attA = ((selA / ssum) - prA) + prA;
        if (!actA) attA = 0.f;
    } else {
        // ======== full 64-entry path ========
        float mx = wredmax(fmaxf(vA, vB));
        float eA = __expf(vA - mx), eB = __expf(vB - mx);
        float S  = wredsum(eA + eB);
        float psA = __fdividef(eA, S), psB = __fdividef(eB, S);

        // bitonic ascending sort of 64 values (v0 = idx lane, v1 = idx lane+32)
        float v0 = vA, v1 = vB;
#pragma unroll
        for (int k = 2; k <= 32; k <<= 1) {
            bool a0 = ((lane & k) == 0);
            bool a1 = (k == 32) ? false : a0;
#pragma unroll
            for (int j = k >> 1; j; j >>= 1) { cas(v0, a0, j, lane); cas(v1, a1, j, lane); }
        }
        {   // k = 64 merge, ascending everywhere
            float lo = fminf(v0, v1), hi = fmaxf(v0, v1); v0 = lo; v1 = hi;
#pragma unroll
            for (int j = 16; j; j >>= 1) { cas(v0, true, j, lane); cas(v1, true, j, lane); }
        }
        float z0 = __shfl_sync(FULLMASK, v1, lane ^ 31);   // descending positions lane
        float z1 = __shfl_sync(FULLMASK, v0, lane ^ 31);   // positions lane+32

        float cz0 = iscan(z0, lane);
        float tot = __shfl_sync(FULLMASK, cz0, 31);
        float cz1 = iscan(z1, lane) + tot;
        float q0  = iscan(z0 * z0, lane);
        float qt  = __shfl_sync(FULLMASK, q0, 31);
        float q1  = iscan(z1 * z1, lane) + qt;

        float kAf = (float)(lane + 1), kBf = (float)(lane + 33);
        float rkA = __fdividef(1.0f, kAf), rkB = __fdividef(1.0f, kBf);
        float mzA = cz0 * rkA, mz2A = q0 * rkA;
        float tcA = mzA - sqrtf(fmaxf(mzA * mzA - mz2A + rkA, 0.f));
        float mzB = cz1 * rkB, mz2B = q1 * rkB;
        float tcB = mzB - sqrtf(fmaxf(mzB * mzB - mz2B + rkB, 0.f));

        int k15 = wredsumi((z0 > tcA ? 1 : 0) + (z1 > tcB ? 1 : 0));
        int ksp = wredsumi(((kAf * z0 > cz0 - 1.0f) ? 1 : 0) + ((kBf * z1 > cz1 - 1.0f) ? 1 : 0));

        int p15 = k15 - 1;
        float tA = __shfl_sync(FULLMASK, tcA, p15 & 31);
        float tB = __shfl_sync(FULLMASK, tcB, p15 & 31);
        float tau15 = (p15 < 32) ? tA : tB;
        int psp = ksp - 1;
        float cA = __shfl_sync(FULLMASK, cz0, psp & 31);
        float cB = __shfl_sync(FULLMASK, cz1, psp & 31);
        float csk = (psp < 32) ? cA : cB;
        float tausp = __fdividef(csk - 1.0f, (float)ksp);

        float r0 = fmaxf(vA - tau15, 0.f); float p15A = r0 * r0;
        float r1 = fmaxf(vB - tau15, 0.f); float p15B = r1 * r1;
        float pspA = fmaxf(vA - tausp, 0.f);
        float pspB = fmaxf(vB - tausp, 0.f);
        float prA, prB;
        if (uu <= 0.5f) {
            float w = uu * 2.0f;
            prA = (1.0f - w) * psA + w * p15A;
            prB = (1.0f - w) * psB + w * p15B;
        } else {
            float w = (uu - 0.5f) * 2.0f;
            prA = (1.0f - w) * p15A + w * pspA;
            prB = (1.0f - w) * p15B + w * pspB;
        }
        float selA = (prA > 1e-6f) ? 1.f : 0.f;
        float selB = (prB > 1e-6f) ? 1.f : 0.f;
        float ssum = wredsum(selA + selB) + 1e-9f;
        attA = ((selA / ssum) - prA) + prA; if (!actA) attA = 0.f;
        attB = ((selB / ssum) - prB) + prB; if (!actB) attB = 0.f;
    }

    // ---- aggregate: lane owns columns 4*lane..4*lane+3; broadcast via shfl ----
    float4 acc = make_float4(0.f, 0.f, 0.f, 0.f);
    const float4* T4 = (const float4*)sTab;
#pragma unroll 2
    for (int i = 0; i < A; i++) {
        float asrc = (i < 32) ? attA : attB;
        int   psrc = (i < 32) ? pkA  : pkB;
        float a = __shfl_sync(FULLMASK, asrc, i & 31);
        int   p = __shfl_sync(FULLMASK, psrc, i & 31);
        if (a != 0.f) {
            float4 t = T4[(p & 15) * 32 + lane];
            float sx = t.x, sy = t.y, sz = t.z, sw = t.w;
            if (!(p & 0x8000)) {
                float4 t1 = T4[(16 + ((p >> 4) & 15)) * 32 + lane];
                float4 t2 = T4[(32 + ((p >> 8) & 15)) * 32 + lane];
                float4 t3 = T4[(48 + ((p >> 12) & 3)) * 32 + lane];
                sx += t1.x + t2.x + t3.x;
                sy += t1.y + t2.y + t3.y;
                sz += t1.z + t2.z + t3.z;
                sw += t1.w + t2.w + t3.w;
            }
            acc.x += a * sx; acc.y += a * sy; acc.z += a * sz; acc.w += a * sw;
        }
    }
    float4 nf = T4[(52 + nc) * 32 + lane];
    float4 no = make_float4(acc.x + nf.x, acc.y + nf.y, acc.z + nf.z, acc.w + nf.w);
    ((float4*)g_agg)[n * 32 + lane] = acc;          // L2-resident for k_edge
    __stcs(((float4*)out_node) + n * 32 + lane, no); // streaming: not re-read
}

// ------------------------ edge output ----------------------------------------
__global__ void k_edge(const int* __restrict__ dst, const float* __restrict__ emb_e,
                       float* __restrict__ out_edge) {
    int idx = blockIdx.x * blockDim.x + threadIdx.x;
    int e = idx >> 5, q = idx & 31;
    if (e >= N_EDGES) return;
    int d = __ldg(dst + e);
    int ec = g_ecode[e];
    float4 a  = __ldg(((const float4*)g_agg) + d * 32 + q);
    float4 em = __ldg(((const float4*)emb_e) + ec * 32 + q);
    float4 o = make_float4(em.x + a.x, em.y + a.y, em.z + a.z, em.w + a.w);
    __stcs(((float4*)out_edge) + (size_t)e * 32 + q, o);
}

// ------------------------ host launch ----------------------------------------
extern "C" void kernel_launch(void* const* d_in, const int* in_sizes, int n_in,
                              void* d_out, int out_size) {
    const int*   node_states = (const int*)d_in[0];
    const int*   edge_states = (const int*)d_in[1];
    const float* scalars     = (const float*)d_in[2];
    const int*   src         = (const int*)d_in[3];
    const int*   dst         = (const int*)d_in[4];
    const int*   rev         = (const int*)d_in[5];
    const int*   slot        = (const int*)d_in[6];
    // d_in[7] = self_loop_idx (identity, unused)

    int w = 8;
    if (w < n_in && in_sizes[w] == 1) w++;   // skip max_deg scalar if present
    const float* emb_v = (const float*)d_in[w + 0];
    const float* emb_b = (const float*)d_in[w + 1];
    const float* emb_e = (const float*)d_in[w + 2];
    const float* emb_s = (const float*)d_in[w + 3];
    const float* Wq    = (const float*)d_in[w + 4];
    const float* Wk    = (const float*)d_in[w + 5];
    const float* Wv    = (const float*)d_in[w + 6];
    const float* Wek   = (const float*)d_in[w + 7];
    const float* Wev   = (const float*)d_in[w + 8];
    const float* Wcf   = (const float*)d_in[w + 9];
    const float* gW1   = (const float*)d_in[w + 10];
    const float* gb1   = (const float*)d_in[w + 11];
    const float* gW2   = (const float*)d_in[w + 12];
    const float* gb2   = (const float*)d_in[w + 13];

    float* out_node = (float*)d_out;
    float* out_edge = (float*)d_out + (size_t)N_NODES * 128;

    k_init<<<(N_NODES * DENSE_STRIDE + 255) / 256, 256>>>(node_states, edge_states);
    k_pre1<<<8, 128>>>(emb_v, emb_b, emb_e, emb_s, Wq, Wk, Wv, Wek, gW1, gb1, Wcf);
    k_pre2<<<4, 128>>>(Wev, gW2, gb2);
    k_pack<<<(N_EDGES + 255) / 256, 256>>>(src, dst, rev, slot, scalars);
    k_attn<<<N_NODES / 16, 512>>>(emb_v, out_node);
    k_edge<<<(N_EDGES * 32) / 256, 256>>>(dst, emb_e, out_edge);
}

// round 5
// speedup vs baseline: 1.7078x; 1.0931x over previous
#include <cuda_runtime.h>
#include <cstdint>

#define N_NODES 20000
#define N_EDGES 340000
#define DENSE_STRIDE 64
#define N_TILES 1250          // 20000 / 16 nodes per tile
#define ATTN_GRID 592         // 148 SMs * 4
#define FULLMASK 0xffffffffu

// ----------------------------- device scratch -------------------------------
__device__ unsigned char  g_ncode[N_NODES];
__device__ unsigned char  g_ecode[N_EDGES];
__device__ int            g_deg[N_NODES];
__device__ unsigned short g_dcode[N_NODES * DENSE_STRIDE];   // no clear needed
__device__ int            g_eid[N_NODES * DENSE_STRIDE];     // no clear needed
__device__ int            g_ctr;

__device__ __align__(16) float g_Qt[2048], g_Kt[2048], g_Vt[2048], g_EKt[2048];
__device__ __align__(16) float g_H1[2048], g_T1[2048], g_T2[2048], g_T3[512];
__device__ __align__(16) float g_Ve1[2048], g_Ve2[2048], g_Vs[512];
__device__ float g_L[256], g_Lself[16], g_u[16];

// ----------------------------- helpers --------------------------------------
__device__ __forceinline__ float wredsum(float v) {
#pragma unroll
    for (int o = 16; o; o >>= 1) v += __shfl_xor_sync(FULLMASK, v, o);
    return v;
}
__device__ __forceinline__ int wredsumi(int v) {
#pragma unroll
    for (int o = 16; o; o >>= 1) v += __shfl_xor_sync(FULLMASK, v, o);
    return v;
}
__device__ __forceinline__ float wredmax(float v) {
#pragma unroll
    for (int o = 16; o; o >>= 1) v = fmaxf(v, __shfl_xor_sync(FULLMASK, v, o));
    return v;
}
__device__ __forceinline__ float iscan(float v, int lane) {
#pragma unroll
    for (int d = 1; d < 32; d <<= 1) {
        float t = __shfl_up_sync(FULLMASK, v, d);
        if (lane >= d) v += t;
    }
    return v;
}
__device__ __forceinline__ void cas(float& v, bool asc, int j, int lane) {
    float pv = __shfl_xor_sync(FULLMASK, v, j);
    bool keepmin = (((lane & j) == 0) == asc);
    v = keepmin ? fminf(v, pv) : fmaxf(v, pv);
}

// ------------------------ init: codes + deg reset ----------------------------
__global__ void k_init(const int* __restrict__ node_states,
                       const int* __restrict__ edge_states) {
    int i = blockIdx.x * blockDim.x + threadIdx.x;
    if (i < N_EDGES) {
        int c = edge_states[i * 4 + 0] + 2 * edge_states[i * 4 + 1] +
                4 * edge_states[i * 4 + 2] + 8 * edge_states[i * 4 + 3];
        g_ecode[i] = (unsigned char)c;
    }
    if (i < N_NODES) {
        int c = node_states[i * 4 + 0] + 2 * node_states[i * 4 + 1] +
                4 * node_states[i * 4 + 2] + 8 * node_states[i * 4 + 3];
        g_ncode[i] = (unsigned char)c;
        g_deg[i] = 0;
    }
    if (i == 0) g_ctr = 0;
}

// ------------------------ precompute stage 1 ---------------------------------
__global__ void k_pre1(const float* __restrict__ emb_v, const float* __restrict__ emb_b,
                       const float* __restrict__ emb_e, const float* __restrict__ emb_s,
                       const float* __restrict__ Wq, const float* __restrict__ Wk,
                       const float* __restrict__ Wv, const float* __restrict__ Wek,
                       const float* __restrict__ gW1, const float* __restrict__ gb1,
                       const float* __restrict__ Wcf) {
    __shared__ float As[16 * 128];
    int t = threadIdx.x, b = blockIdx.x;
    const float* W = 0; float* out = 0; int rows = 16;
    const float* bias = 0; bool do_relu = false;
#pragma unroll
    for (int r = 0; r < 16; r++) As[r * 128 + t] = 0.f;
    switch (b) {
        case 0: for (int r = 0; r < 16; r++) As[r*128+t] = emb_v[2*r*128 + t];
                W = Wq;  out = g_Qt;  break;
        case 1: for (int r = 0; r < 16; r++) As[r*128+t] = emb_v[2*r*128 + t];
                W = Wk;  out = g_Kt;  break;
        case 2: for (int r = 0; r < 16; r++) As[r*128+t] = emb_v[2*r*128 + t];
                W = Wv;  out = g_Vt;  break;
        case 3: for (int r = 0; r < 16; r++) As[r*128+t] = emb_b[2*r*128 + t];
                W = Wek; out = g_EKt; break;
        case 4: for (int r = 0; r < 16; r++) As[r*128+t] = emb_v[2*r*128 + t];
                W = gW1; out = g_H1; bias = gb1; do_relu = true; break;
        case 5: for (int r = 0; r < 16; r++) As[r*128+t] = emb_e[r*128 + t];
                W = Wcf;               out = g_T1; break;
        case 6: for (int r = 0; r < 16; r++) As[r*128+t] = emb_e[r*128 + t];
                W = Wcf + 128 * 128;   out = g_T2; break;
        case 7: for (int r = 0; r < 4;  r++) As[r*128+t] = emb_s[r*128 + t];
                W = Wcf + 256 * 128;   out = g_T3; rows = 4; break;
    }
    __syncthreads();
    float acc[16];
#pragma unroll
    for (int r = 0; r < 16; r++) acc[r] = 0.f;
    for (int k = 0; k < 128; k++) {
        float w = W[k * 128 + t];
#pragma unroll
        for (int r = 0; r < 16; r++) acc[r] += As[r * 128 + k] * w;
    }
    for (int r = 0; r < rows; r++) {
        float v = acc[r];
        if (bias) v += bias[t];
        if (do_relu) v = fmaxf(v, 0.f);
        out[r * 128 + t] = v;
    }
}

// ------------------------ precompute stage 2 ---------------------------------
__global__ void k_pre2(const float* __restrict__ Wev,
                       const float* __restrict__ gW2, const float* __restrict__ gb2) {
    __shared__ float As[16 * 128];
    __shared__ float Bs[16 * 128];
    int t = threadIdx.x, b = blockIdx.x;
    if (b < 3) {
        const float* src = (b == 0) ? g_T1 : (b == 1) ? g_T2 : g_T3;
        int rows = (b == 2) ? 4 : 16;
        for (int r = 0; r < 16; r++) As[r * 128 + t] = (r < rows) ? src[r * 128 + t] : 0.f;
        __syncthreads();
        float acc[16];
#pragma unroll
        for (int r = 0; r < 16; r++) acc[r] = 0.f;
        for (int k = 0; k < 128; k++) {
            float w = Wev[k * 128 + t];
#pragma unroll
            for (int r = 0; r < 16; r++) acc[r] += As[r * 128 + k] * w;
        }
        float* out = (b == 0) ? g_Ve1 : (b == 1) ? g_Ve2 : g_Vs;
        for (int r = 0; r < rows; r++) out[r * 128 + t] = acc[r];
    } else {
        for (int r = 0; r < 16; r++) {
            As[r * 128 + t] = g_Qt[r * 128 + t];
            Bs[r * 128 + t] = g_Kt[r * 128 + t] + g_EKt[r * 128 + t];
        }
        __syncthreads();
        const float SH = 11.31370849898476f;   // sqrt(128)
#pragma unroll
        for (int pi = 0; pi < 2; pi++) {
            int p = t + pi * 128;
            int qc = p >> 4, sc = p & 15;
            float a = 0.f;
            for (int k = 0; k < 128; k++) a += As[qc * 128 + k] * Bs[sc * 128 + k];
            g_L[p] = a / SH;
        }
        if (t < 16) {
            float a = 0.f;
            for (int k = 0; k < 128; k++) a += As[t * 128 + k] * g_Kt[t * 128 + k];
            g_Lself[t] = a / SH;
            float h = 0.f;
            for (int k = 0; k < 128; k++) h += g_H1[t * 128 + k] * gW2[k];
            h += gb2[0];
            g_u[t] = 1.0f / (1.0f + expf(-h));
        }
    }
}

// ------------------------ pack + scatter -------------------------------------
__global__ void k_pack(const int* __restrict__ src, const int* __restrict__ dst,
                       const int* __restrict__ rev, const int* __restrict__ slot,
                       const float* __restrict__ scalars) {
    int e = blockIdx.x * blockDim.x + threadIdx.x;
    if (e >= N_EDGES) return;
    int s_ = __ldg(src + e), d_ = __ldg(dst + e);
    int r_ = __ldg(rev + e);
    int sl = __ldg(slot + e);
    float sv = __ldg(scalars + e);
    int sc = g_ncode[s_];
    int ec = g_ecode[e];
    int rc = g_ecode[r_];
    float rs = __ldg(scalars + d_);
    float ss = __ldg(scalars + s_);
    int rlx  = (sv < rs) ? 1 : 0;
    int rlxd = ((ss + sv) < rs) ? 1 : 0;
    int stc = rlx | (rlxd << 1);
    int pk = sc | (ec << 4) | (rc << 8) | (stc << 12);
    if (sl < DENSE_STRIDE - 1) {
        g_dcode[d_ * DENSE_STRIDE + sl] = (unsigned short)pk;
        g_eid[d_ * DENSE_STRIDE + sl] = e;
        atomicMax(&g_deg[d_], sl + 1);
    }
}

// ------------------------ fused attention + outputs --------------------------
// Persistent: ATTN_GRID blocks, 512 threads = 16 warps = 16 nodes per tile,
// work-stealing via g_ctr. Tables loaded into smem ONCE per block.
__global__ __launch_bounds__(512, 2) void k_attn(const float* __restrict__ emb_v,
                                                 const float* __restrict__ emb_e,
                                                 float* __restrict__ out_node,
                                                 float* __restrict__ out_edge) {
    // sTab rows: 0..15 Vt | 16..31 Ve1 | 32..47 Ve2 | 48..51 Vs | 52..67 EmbE
    __shared__ float sTab[68 * 128];
    __shared__ float sL[256];
    __shared__ float sLs[16];
    __shared__ float sU[16];
    __shared__ float sAtt[16][64];
    __shared__ unsigned short sPk[16][64];
    __shared__ int sEid[16][64];
    __shared__ int sTile;

    int tid = threadIdx.x;
    for (int i = tid; i < 68 * 128; i += 512) {
        int row = i >> 7, col = i & 127;
        float v;
        if      (row < 16) v = g_Vt[i];
        else if (row < 32) v = g_Ve1[(row - 16) * 128 + col];
        else if (row < 48) v = g_Ve2[(row - 32) * 128 + col];
        else if (row < 52) v = g_Vs[(row - 48) * 128 + col];
        else               v = emb_e[(row - 52) * 128 + col];
        sTab[i] = v;
    }
    if (tid < 256) sL[tid] = g_L[tid];
    if (tid < 16) { sLs[tid] = g_Lself[tid]; sU[tid] = g_u[tid]; }

    int warp = tid >> 5, lane = tid & 31;
    const float4* T4 = (const float4*)sTab;

    for (;;) {
        __syncthreads();                 // protect sTile + staging reuse
        if (tid == 0) sTile = atomicAdd(&g_ctr, 1);
        __syncthreads();
        int tile = sTile;
        if (tile >= N_TILES) break;

        int n = tile * 16 + warp;
        int nc = g_ncode[n];
        int deg = g_deg[n];
        int A = deg + 1;                 // entry 0 = self
        int base = n * DENSE_STRIDE;
        int ia = lane ? (lane - 1) : 0;

        // ---- gather entries ----
        const unsigned short ca = g_dcode[base + ia];
        const int ea            = g_eid  [base + ia];
        const unsigned short cb = g_dcode[base + lane + 31];
        const int eb            = g_eid  [base + lane + 31];
        bool actA = (lane == 0) || (lane - 1 < deg);
        bool actB = (lane + 31 < deg);
        float vA = (lane == 0) ? sLs[nc] : (actA ? sL[(nc << 4) | (ca & 15)] : -1e9f);
        float vB = actB ? sL[(nc << 4) | (cb & 15)] : -1e9f;
        float uu = sU[nc];

        float attA = 0.f, attB = 0.f;

        if (A <= 32) {
            // ---- fast path: all entries in vA ----
            float mx = wredmax(vA);
            float eAx = __expf(vA - mx);
            float S  = wredsum(eAx);
            float psA = __fdividef(eAx, S);

            float v = vA;
#pragma unroll
            for (int k = 2; k <= 32; k <<= 1) {
                bool asc = ((lane & k) == 0);
#pragma unroll
                for (int j = k >> 1; j; j >>= 1) cas(v, asc, j, lane);
            }
            float z = __shfl_sync(FULLMASK, v, lane ^ 31);     // descending

            float cz = iscan(z, lane);
            float q  = iscan(z * z, lane);
            float kf = (float)(lane + 1);
            float rk = __fdividef(1.0f, kf);
            float mz = cz * rk, mz2 = q * rk;
            float tc = mz - sqrtf(fmaxf(mz * mz - mz2 + rk, 0.f));

            int k15 = wredsumi(z > tc ? 1 : 0);
            int ksp = wredsumi((kf * z > cz - 1.0f) ? 1 : 0);
            float tau15 = __shfl_sync(FULLMASK, tc, k15 - 1);
            float csk   = __shfl_sync(FULLMASK, cz, ksp - 1);
            float tausp = __fdividef(csk - 1.0f, (float)ksp);

            float r0 = fmaxf(vA - tau15, 0.f); float p15A = r0 * r0;
            float pspA = fmaxf(vA - tausp, 0.f);
            float prA;
            if (uu <= 0.5f) { float w = uu * 2.0f;          prA = (1.0f - w) * psA + w * p15A; }
            else            { float w = (uu - 0.5f) * 2.0f; prA = (1.0f - w) * p15A + w * pspA; }
            float selA = (prA > 1e-6f) ? 1.f : 0.f;
            float ssum = wredsum(selA) + 1e-9f;
            attA = ((selA / ssum) - prA) + prA;
            if (!actA) attA = 0.f;
        } else {
            // ---- full 64-entry path ----
            float mx = wredmax(fmaxf(vA, vB));
            float eAx = __expf(vA - mx), eBx = __expf(vB - mx);
            float S  = wredsum(eAx + eBx);
            float psA = __fdividef(eAx, S), psB = __fdividef(eBx, S);

            float v0 = vA, v1 = vB;
#pragma unroll
            for (int k = 2; k <= 32; k <<= 1) {
                bool a0 = ((lane & k) == 0);
                bool a1 = (k == 32) ? false : a0;
#pragma unroll
                for (int j = k >> 1; j; j >>= 1) { cas(v0, a0, j, lane); cas(v1, a1, j, lane); }
            }
            {
                float lo = fminf(v0, v1), hi = fmaxf(v0, v1); v0 = lo; v1 = hi;
#pragma unroll
                for (int j = 16; j; j >>= 1) { cas(v0, true, j, lane); cas(v1, true, j, lane); }
            }
            float z0 = __shfl_sync(FULLMASK, v1, lane ^ 31);
            float z1 = __shfl_sync(FULLMASK, v0, lane ^ 31);

            float cz0 = iscan(z0, lane);
            float tot = __shfl_sync(FULLMASK, cz0, 31);
            float cz1 = iscan(z1, lane) + tot;
            float q0  = iscan(z0 * z0, lane);
            float qt  = __shfl_sync(FULLMASK, q0, 31);
            float q1  = iscan(z1 * z1, lane) + qt;

            float kAf = (float)(lane + 1), kBf = (float)(lane + 33);
            float rkA = __fdividef(1.0f, kAf), rkB = __fdividef(1.0f, kBf);
            float mzA = cz0 * rkA, mz2A = q0 * rkA;
            float tcA = mzA - sqrtf(fmaxf(mzA * mzA - mz2A + rkA, 0.f));
            float mzB = cz1 * rkB, mz2B = q1 * rkB;
            float tcB = mzB - sqrtf(fmaxf(mzB * mzB - mz2B + rkB, 0.f));

            int k15 = wredsumi((z0 > tcA ? 1 : 0) + (z1 > tcB ? 1 : 0));
            int ksp = wredsumi(((kAf * z0 > cz0 - 1.0f) ? 1 : 0) + ((kBf * z1 > cz1 - 1.0f) ? 1 : 0));

            int p15 = k15 - 1;
            float tA = __shfl_sync(FULLMASK, tcA, p15 & 31);
            float tB = __shfl_sync(FULLMASK, tcB, p15 & 31);
            float tau15 = (p15 < 32) ? tA : tB;
            int psp = ksp - 1;
            float cA = __shfl_sync(FULLMASK, cz0, psp & 31);
            float cB = __shfl_sync(FULLMASK, cz1, psp & 31);
            float csk = (psp < 32) ? cA : cB;
            float tausp = __fdividef(csk - 1.0f, (float)ksp);

            float r0 = fmaxf(vA - tau15, 0.f); float p15A = r0 * r0;
            float r1 = fmaxf(vB - tau15, 0.f); float p15B = r1 * r1;
            float pspA = fmaxf(vA - tausp, 0.f);
            float pspB = fmaxf(vB - tausp, 0.f);
            float prA, prB;
            if (uu <= 0.5f) {
                float w = uu * 2.0f;
                prA = (1.0f - w) * psA + w * p15A;
                prB = (1.0f - w) * psB + w * p15B;
            } else {
                float w = (uu - 0.5f) * 2.0f;
                prA = (1.0f - w) * p15A + w * pspA;
                prB = (1.0f - w) * p15B + w * pspB;
            }
            float selA = (prA > 1e-6f) ? 1.f : 0.f;
            float selB = (prB > 1e-6f) ? 1.f : 0.f;
            float ssum = wredsum(selA + selB) + 1e-9f;
            attA = ((selA / ssum) - prA) + prA; if (!actA) attA = 0.f;
            attB = ((selB / ssum) - prB) + prB; if (!actB) attB = 0.f;
        }

        // ---- stage per-entry data for indexed access ----
        sAtt[warp][lane] = attA;  sAtt[warp][lane + 32] = attB;
        sPk[warp][lane]  = ca;    sPk[warp][lane + 32]  = cb;
        sEid[warp][lane] = ea;    sEid[warp][lane + 32] = eb;
        __syncwarp();

        // ---- aggregate (lane owns columns 4*lane..4*lane+3) ----
        float a0 = sAtt[warp][0];
        float4 acc = make_float4(0.f, 0.f, 0.f, 0.f);
        if (a0 != 0.f) {
            float4 t = T4[nc * 32 + lane];
            acc.x = a0 * t.x; acc.y = a0 * t.y; acc.z = a0 * t.z; acc.w = a0 * t.w;
        }
#pragma unroll 2
        for (int i = 1; i < A; i++) {
            float a = sAtt[warp][i];
            if (a != 0.f) {
                int p = sPk[warp][i];
                float4 t0 = T4[(p & 15) * 32 + lane];
                float4 t1 = T4[(16 + ((p >> 4) & 15)) * 32 + lane];
                float4 t2 = T4[(32 + ((p >> 8) & 15)) * 32 + lane];
                float4 t3 = T4[(48 + ((p >> 12) & 3)) * 32 + lane];
                acc.x += a * (t0.x + t1.x + t2.x + t3.x);
                acc.y += a * (t0.y + t1.y + t2.y + t3.y);
                acc.z += a * (t0.z + t1.z + t2.z + t3.z);
                acc.w += a * (t0.w + t1.w + t2.w + t3.w);
            }
        }

        // ---- node output: node_fts + agg ----
        float4 nf = __ldg(((const float4*)emb_v) + (2 * nc) * 32 + lane);
        float4 no = make_float4(acc.x + nf.x, acc.y + nf.y, acc.z + nf.z, acc.w + nf.w);
        __stcs(((float4*)out_node) + n * 32 + lane, no);

        // ---- edge outputs: emb_e[ec] + agg, written directly per edge ----
#pragma unroll 2
        for (int i = 1; i < A; i++) {
            int p = sPk[warp][i];
            int e = sEid[warp][i];
            float4 t = T4[(52 + ((p >> 4) & 15)) * 32 + lane];
            float4 o = make_float4(acc.x + t.x, acc.y + t.y, acc.z + t.z, acc.w + t.w);
            __stcs(((float4*)out_edge) + (size_t)e * 32 + lane, o);
        }
    }
}

// ------------------------ host launch ----------------------------------------
extern "C" void kernel_launch(void* const* d_in, const int* in_sizes, int n_in,
                              void* d_out, int out_size) {
    const int*   node_states = (const int*)d_in[0];
    const int*   edge_states = (const int*)d_in[1];
    const float* scalars     = (const float*)d_in[2];
    const int*   src         = (const int*)d_in[3];
    const int*   dst         = (const int*)d_in[4];
    const int*   rev         = (const int*)d_in[5];
    const int*   slot        = (const int*)d_in[6];
    // d_in[7] = self_loop_idx (identity, unused)

    int w = 8;
    if (w < n_in && in_sizes[w] == 1) w++;   // skip max_deg scalar if present
    const float* emb_v = (const float*)d_in[w + 0];
    const float* emb_b = (const float*)d_in[w + 1];
    const float* emb_e = (const float*)d_in[w + 2];
    const float* emb_s = (const float*)d_in[w + 3];
    const float* Wq    = (const float*)d_in[w + 4];
    const float* Wk    = (const float*)d_in[w + 5];
    const float* Wv    = (const float*)d_in[w + 6];
    const float* Wek   = (const float*)d_in[w + 7];
    const float* Wev   = (const float*)d_in[w + 8];
    const float* Wcf   = (const float*)d_in[w + 9];
    const float* gW1   = (const float*)d_in[w + 10];
    const float* gb1   = (const float*)d_in[w + 11];
    const float* gW2   = (const float*)d_in[w + 12];
    const float* gb2   = (const float*)d_in[w + 13];

    float* out_node = (float*)d_out;
    float* out_edge = (float*)d_out + (size_t)N_NODES * 128;

    k_init<<<(N_EDGES + 255) / 256, 256>>>(node_states, edge_states);
    k_pre1<<<8, 128>>>(emb_v, emb_b, emb_e, emb_s, Wq, Wk, Wv, Wek, gW1, gb1, Wcf);
    k_pre2<<<4, 128>>>(Wev, gW2, gb2);
    k_pack<<<(N_EDGES + 255) / 256, 256>>>(src, dst, rev, slot, scalars);
    k_attn<<<ATTN_GRID, 512>>>(emb_v, emb_e, out_node, out_edge);
}

// round 11
// speedup vs baseline: 1.7958x; 1.0516x over previous
#include <cuda_runtime.h>
#include <cstdint>

#define N_NODES 20000
#define N_EDGES 340000
#define DENSE_STRIDE 64
#define ATTN_BLOCKS 296        // 148 SMs * 2 resident blocks
#define N_WARPS (ATTN_BLOCKS * 16)
#define FULLMASK 0xffffffffu

// ----------------------------- device scratch -------------------------------
__device__ unsigned char  g_ncode[N_NODES];
__device__ unsigned char  g_ecode[N_EDGES];
__device__ int            g_deg[N_NODES];
__device__ unsigned short g_dcode[N_NODES * DENSE_STRIDE];   // no clear needed
__device__ int            g_eid[N_NODES * DENSE_STRIDE];     // no clear needed

__device__ __align__(16) float g_Qt[2048], g_Kt[2048], g_Vt[2048], g_EKt[2048];
__device__ __align__(16) float g_H1[2048], g_T1[2048], g_T2[2048], g_T3[512];
__device__ __align__(16) float g_Ve1[2048], g_Ve2[2048], g_Vs[512];
__device__ float g_L[256], g_Lself[16], g_u[16];

// ----------------------------- helpers --------------------------------------
__device__ __forceinline__ float wredsum(float v) {
#pragma unroll
    for (int o = 16; o; o >>= 1) v += __shfl_xor_sync(FULLMASK, v, o);
    return v;
}
__device__ __forceinline__ int wredsumi(int v) {
#pragma unroll
    for (int o = 16; o; o >>= 1) v += __shfl_xor_sync(FULLMASK, v, o);
    return v;
}
__device__ __forceinline__ float wredmax(float v) {
#pragma unroll
    for (int o = 16; o; o >>= 1) v = fmaxf(v, __shfl_xor_sync(FULLMASK, v, o));
    return v;
}
__device__ __forceinline__ float iscan(float v, int lane) {
#pragma unroll
    for (int d = 1; d < 32; d <<= 1) {
        float t = __shfl_up_sync(FULLMASK, v, d);
        if (lane >= d) v += t;
    }
    return v;
}
__device__ __forceinline__ void cas(float& v, bool asc, int j, int lane) {
    float pv = __shfl_xor_sync(FULLMASK, v, j);
    bool keepmin = (((lane & j) == 0) == asc);
    v = keepmin ? fminf(v, pv) : fmaxf(v, pv);
}

// ------------------------ init: codes + deg reset ----------------------------
__global__ void k_init(const int* __restrict__ node_states,
                       const int* __restrict__ edge_states) {
    int i = blockIdx.x * blockDim.x + threadIdx.x;
    if (i < N_EDGES) {
        int c = edge_states[i * 4 + 0] + 2 * edge_states[i * 4 + 1] +
                4 * edge_states[i * 4 + 2] + 8 * edge_states[i * 4 + 3];
        g_ecode[i] = (unsigned char)c;
    }
    if (i < N_NODES) {
        int c = node_states[i * 4 + 0] + 2 * node_states[i * 4 + 1] +
                4 * node_states[i * 4 + 2] + 8 * node_states[i * 4 + 3];
        g_ncode[i] = (unsigned char)c;
        g_deg[i] = 0;
    }
}

// ------------------------ precompute stage 1 ---------------------------------
__global__ void k_pre1(const float* __restrict__ emb_v, const float* __restrict__ emb_b,
                       const float* __restrict__ emb_e, const float* __restrict__ emb_s,
                       const float* __restrict__ Wq, const float* __restrict__ Wk,
                       const float* __restrict__ Wv, const float* __restrict__ Wek,
                       const float* __restrict__ gW1, const float* __restrict__ gb1,
                       const float* __restrict__ Wcf) {
    __shared__ float As[16 * 128];
    int t = threadIdx.x, b = blockIdx.x;
    const float* W = 0; float* out = 0; int rows = 16;
    const float* bias = 0; bool do_relu = false;
#pragma unroll
    for (int r = 0; r < 16; r++) As[r * 128 + t] = 0.f;
    switch (b) {
        case 0: for (int r = 0; r < 16; r++) As[r*128+t] = emb_v[2*r*128 + t];
                W = Wq;  out = g_Qt;  break;
        case 1: for (int r = 0; r < 16; r++) As[r*128+t] = emb_v[2*r*128 + t];
                W = Wk;  out = g_Kt;  break;
        case 2: for (int r = 0; r < 16; r++) As[r*128+t] = emb_v[2*r*128 + t];
                W = Wv;  out = g_Vt;  break;
        case 3: for (int r = 0; r < 16; r++) As[r*128+t] = emb_b[2*r*128 + t];
                W = Wek; out = g_EKt; break;
        case 4: for (int r = 0; r < 16; r++) As[r*128+t] = emb_v[2*r*128 + t];
                W = gW1; out = g_H1; bias = gb1; do_relu = true; break;
        case 5: for (int r = 0; r < 16; r++) As[r*128+t] = emb_e[r*128 + t];
                W = Wcf;               out = g_T1; break;
        case 6: for (int r = 0; r < 16; r++) As[r*128+t] = emb_e[r*128 + t];
                W = Wcf + 128 * 128;   out = g_T2; break;
        case 7: for (int r = 0; r < 4;  r++) As[r*128+t] = emb_s[r*128 + t];
                W = Wcf + 256 * 128;   out = g_T3; rows = 4; break;
    }
    __syncthreads();
    float acc[16];
#pragma unroll
    for (int r = 0; r < 16; r++) acc[r] = 0.f;
    for (int k = 0; k < 128; k++) {
        float w = W[k * 128 + t];
#pragma unroll
        for (int r = 0; r < 16; r++) acc[r] += As[r * 128 + k] * w;
    }
    for (int r = 0; r < rows; r++) {
        float v = acc[r];
        if (bias) v += bias[t];
        if (do_relu) v = fmaxf(v, 0.f);
        out[r * 128 + t] = v;
    }
}

// ------------------------ precompute stage 2 ---------------------------------
__global__ void k_pre2(const float* __restrict__ Wev,
                       const float* __restrict__ gW2, const float* __restrict__ gb2) {
    __shared__ float As[16 * 128];
    __shared__ float Bs[16 * 128];
    int t = threadIdx.x, b = blockIdx.x;
    if (b < 3) {
        const float* src = (b == 0) ? g_T1 : (b == 1) ? g_T2 : g_T3;
        int rows = (b == 2) ? 4 : 16;
        for (int r = 0; r < 16; r++) As[r * 128 + t] = (r < rows) ? src[r * 128 + t] : 0.f;
        __syncthreads();
        float acc[16];
#pragma unroll
        for (int r = 0; r < 16; r++) acc[r] = 0.f;
        for (int k = 0; k < 128; k++) {
            float w = Wev[k * 128 + t];
#pragma unroll
            for (int r = 0; r < 16; r++) acc[r] += As[r * 128 + k] * w;
        }
        float* out = (b == 0) ? g_Ve1 : (b == 1) ? g_Ve2 : g_Vs;
        for (int r = 0; r < rows; r++) out[r * 128 + t] = acc[r];
    } else {
        for (int r = 0; r < 16; r++) {
            As[r * 128 + t] = g_Qt[r * 128 + t];
            Bs[r * 128 + t] = g_Kt[r * 128 + t] + g_EKt[r * 128 + t];
        }
        __syncthreads();
        const float SH = 11.31370849898476f;   // sqrt(128)
#pragma unroll
        for (int pi = 0; pi < 2; pi++) {
            int p = t + pi * 128;
            int qc = p >> 4, sc = p & 15;
            float a = 0.f;
            for (int k = 0; k < 128; k++) a += As[qc * 128 + k] * Bs[sc * 128 + k];
            g_L[p] = a / SH;
        }
        if (t < 16) {
            float a = 0.f;
            for (int k = 0; k < 128; k++) a += As[t * 128 + k] * g_Kt[t * 128 + k];
            g_Lself[t] = a / SH;
            float h = 0.f;
            for (int k = 0; k < 128; k++) h += g_H1[t * 128 + k] * gW2[k];
            h += gb2[0];
            g_u[t] = 1.0f / (1.0f + expf(-h));
        }
    }
}

// ------------------------ pack + scatter (2 edges/thread for MLP) ------------
__global__ void k_pack(const int* __restrict__ src, const int* __restrict__ dst,
                       const int* __restrict__ rev, const int* __restrict__ slot,
                       const float* __restrict__ scalars) {
    int base = (blockIdx.x * blockDim.x + threadIdx.x) * 2;
#pragma unroll
    for (int k = 0; k < 2; k++) {
        int e = base + k;
        if (e < N_EDGES) {
            int s_ = __ldg(src + e), d_ = __ldg(dst + e);
            int r_ = __ldg(rev + e);
            int sl = __ldg(slot + e);
            float sv = __ldg(scalars + e);
            int sc = g_ncode[s_];
            int ec = g_ecode[e];
            int rc = g_ecode[r_];
            float rs = __ldg(scalars + d_);
            float ss = __ldg(scalars + s_);
            int rlx  = (sv < rs) ? 1 : 0;
            int rlxd = ((ss + sv) < rs) ? 1 : 0;
            int stc = rlx | (rlxd << 1);
            int pk = sc | (ec << 4) | (rc << 8) | (stc << 12);
            if (sl < DENSE_STRIDE - 1) {
                g_dcode[d_ * DENSE_STRIDE + sl] = (unsigned short)pk;
                g_eid[d_ * DENSE_STRIDE + sl] = e;
                atomicMax(&g_deg[d_], sl + 1);
            }
        }
    }
}

// ------------------------ fused attention + outputs --------------------------
// Persistent, STATIC per-warp schedule: warp w handles nodes w, w+N_WARPS, ...
// No barriers after the one-time table load; warps fully independent.
__global__ __launch_bounds__(512, 2) void k_attn(const float* __restrict__ emb_v,
                                                 const float* __restrict__ emb_e,
                                                 float* __restrict__ out_node,
                                                 float* __restrict__ out_edge) {
    // sTab rows: 0..15 Vt | 16..31 Ve1 | 32..47 Ve2 | 48..51 Vs | 52..67 EmbE
    __shared__ float sTab[68 * 128];
    __shared__ float sL[256];
    __shared__ float sLs[16];
    __shared__ float sU[16];
    __shared__ float sAtt[16][64];
    __shared__ unsigned short sPk[16][64];
    __shared__ int sEid[16][64];

    int tid = threadIdx.x;
    for (int i = tid; i < 68 * 128; i += 512) {
        int row = i >> 7, col = i & 127;
        float v;
        if      (row < 16) v = g_Vt[i];
        else if (row < 32) v = g_Ve1[(row - 16) * 128 + col];
        else if (row < 48) v = g_Ve2[(row - 32) * 128 + col];
        else if (row < 52) v = g_Vs[(row - 48) * 128 + col];
        else               v = emb_e[(row - 52) * 128 + col];
        sTab[i] = v;
    }
    if (tid < 256) sL[tid] = g_L[tid];
    if (tid < 16) { sLs[tid] = g_Lself[tid]; sU[tid] = g_u[tid]; }
    __syncthreads();                     // only block-wide sync in the kernel

    int warp = tid >> 5, lane = tid & 31;
    int gwarp = blockIdx.x * 16 + warp;
    const float4* T4 = (const float4*)sTab;

    for (int n = gwarp; n < N_NODES; n += N_WARPS) {
        int nc = g_ncode[n];
        int deg = g_deg[n];
        int A = deg + 1;                 // entry 0 = self
        int base = n * DENSE_STRIDE;
        int iA = base + (lane ? (lane - 1) : 0);
        int iB = base + lane + 31;

        // ---- gather entries ----
        const unsigned short ca = g_dcode[iA];
        const int ea            = g_eid  [iA];
        const unsigned short cb = g_dcode[iB];
        const int eb            = g_eid  [iB];
        bool actA = (lane == 0) || (lane - 1 < deg);
        bool actB = (lane + 31 < deg);
        float vA = (lane == 0) ? sLs[nc] : (actA ? sL[(nc << 4) | (ca & 15)] : -1e9f);
        float vB = actB ? sL[(nc << 4) | (cb & 15)] : -1e9f;
        float uu = sU[nc];

        float attA = 0.f, attB = 0.f;

        if (A <= 32) {
            // ---- fast path: all entries in vA ----
            float mx = wredmax(vA);
            float eAx = __expf(vA - mx);
            float S  = wredsum(eAx);
            float psA = __fdividef(eAx, S);

            float v = vA;
#pragma unroll
            for (int k = 2; k <= 32; k <<= 1) {
                bool asc = ((lane & k) == 0);
#pragma unroll
                for (int j = k >> 1; j; j >>= 1) cas(v, asc, j, lane);
            }
            float z = __shfl_sync(FULLMASK, v, lane ^ 31);     // descending

            float cz = iscan(z, lane);
            float q  = iscan(z * z, lane);
            float kf = (float)(lane + 1);
            float rk = __fdividef(1.0f, kf);
            float mz = cz * rk, mz2 = q * rk;
            float tc = mz - sqrtf(fmaxf(mz * mz - mz2 + rk, 0.f));

            int k15 = wredsumi(z > tc ? 1 : 0);
            int ksp = wredsumi((kf * z > cz - 1.0f) ? 1 : 0);
            float tau15 = __shfl_sync(FULLMASK, tc, k15 - 1);
            float csk   = __shfl_sync(FULLMASK, cz, ksp - 1);
            float tausp = __fdividef(csk - 1.0f, (float)ksp);

            float r0 = fmaxf(vA - tau15, 0.f); float p15A = r0 * r0;
            float pspA = fmaxf(vA - tausp, 0.f);
            float prA;
            if (uu <= 0.5f) { float w = uu * 2.0f;          prA = (1.0f - w) * psA + w * p15A; }
            else            { float w = (uu - 0.5f) * 2.0f; prA = (1.0f - w) * p15A + w * pspA; }
            float selA = (prA > 1e-6f) ? 1.f : 0.f;
            float ssum = wredsum(selA) + 1e-9f;
            attA = ((selA / ssum) - prA) + prA;
            if (!actA) attA = 0.f;
        } else {
            // ---- full 64-entry path ----
            float mx = wredmax(fmaxf(vA, vB));
            float eAx = __expf(vA - mx), eBx = __expf(vB - mx);
            float S  = wredsum(eAx + eBx);
            float psA = __fdividef(eAx, S), psB = __fdividef(eBx, S);

            float v0 = vA, v1 = vB;
#pragma unroll
            for (int k = 2; k <= 32; k <<= 1) {
                bool a0 = ((lane & k) == 0);
                bool a1 = (k == 32) ? false : a0;
#pragma unroll
                for (int j = k >> 1; j; j >>= 1) { cas(v0, a0, j, lane); cas(v1, a1, j, lane); }
            }
            {
                float lo = fminf(v0, v1), hi = fmaxf(v0, v1); v0 = lo; v1 = hi;
#pragma unroll
                for (int j = 16; j; j >>= 1) { cas(v0, true, j, lane); cas(v1, true, j, lane); }
            }
            float z0 = __shfl_sync(FULLMASK, v1, lane ^ 31);
            float z1 = __shfl_sync(FULLMASK, v0, lane ^ 31);

            float cz0 = iscan(z0, lane);
            float tot = __shfl_sync(FULLMASK, cz0, 31);
            float cz1 = iscan(z1, lane) + tot;
            float q0  = iscan(z0 * z0, lane);
            float qt  = __shfl_sync(FULLMASK, q0, 31);
            float q1  = iscan(z1 * z1, lane) + qt;

            float kAf = (float)(lane + 1), kBf = (float)(lane + 33);
            float rkA = __fdividef(1.0f, kAf), rkB = __fdividef(1.0f, kBf);
            float mzA = cz0 * rkA, mz2A = q0 * rkA;
            float tcA = mzA - sqrtf(fmaxf(mzA * mzA - mz2A + rkA, 0.f));
            float mzB = cz1 * rkB, mz2B = q1 * rkB;
            float tcB = mzB - sqrtf(fmaxf(mzB * mzB - mz2B + rkB, 0.f));

            int k15 = wredsumi((z0 > tcA ? 1 : 0) + (z1 > tcB ? 1 : 0));
            int ksp = wredsumi(((kAf * z0 > cz0 - 1.0f) ? 1 : 0) + ((kBf * z1 > cz1 - 1.0f) ? 1 : 0));

            int p15 = k15 - 1;
            float tA = __shfl_sync(FULLMASK, tcA, p15 & 31);
            float tB = __shfl_sync(FULLMASK, tcB, p15 & 31);
            float tau15 = (p15 < 32) ? tA : tB;
            int psp = ksp - 1;
            float cA = __shfl_sync(FULLMASK, cz0, psp & 31);
            float cB = __shfl_sync(FULLMASK, cz1, psp & 31);
            float csk = (psp < 32) ? cA : cB;
            float tausp = __fdividef(csk - 1.0f, (float)ksp);

            float r0 = fmaxf(vA - tau15, 0.f); float p15A = r0 * r0;
            float r1 = fmaxf(vB - tau15, 0.f); float p15B = r1 * r1;
            float pspA = fmaxf(vA - tausp, 0.f);
            float pspB = fmaxf(vB - tausp, 0.f);
            float prA, prB;
            if (uu <= 0.5f) {
                float w = uu * 2.0f;
                prA = (1.0f - w) * psA + w * p15A;
                prB = (1.0f - w) * psB + w * p15B;
            } else {
                float w = (uu - 0.5f) * 2.0f;
                prA = (1.0f - w) * p15A + w * pspA;
                prB = (1.0f - w) * p15B + w * pspB;
            }
            float selA = (prA > 1e-6f) ? 1.f : 0.f;
            float selB = (prB > 1e-6f) ? 1.f : 0.f;
            float ssum = wredsum(selA + selB) + 1e-9f;
            attA = ((selA / ssum) - prA) + prA; if (!actA) attA = 0.f;
            attB = ((selB / ssum) - prB) + prB; if (!actB) attB = 0.f;
        }

        // ---- stage per-entry data (warp-private; only __syncwarp needed) ----
        sAtt[warp][lane] = attA;  sAtt[warp][lane + 32] = attB;
        sPk[warp][lane]  = ca;    sPk[warp][lane + 32]  = cb;
        sEid[warp][lane] = ea;    sEid[warp][lane + 32] = eb;
        __syncwarp();

        // ---- aggregate (lane owns columns 4*lane..4*lane+3) ----
        float a0 = sAtt[warp][0];
        float4 acc = make_float4(0.f, 0.f, 0.f, 0.f);
        if (a0 != 0.f) {
            float4 t = T4[nc * 32 + lane];
            acc.x = a0 * t.x; acc.y = a0 * t.y; acc.z = a0 * t.z; acc.w = a0 * t.w;
        }
#pragma unroll 2
        for (int i = 1; i < A; i++) {
            float a = sAtt[warp][i];
            if (a != 0.f) {
                int p = sPk[warp][i];
                float4 t0 = T4[(p & 15) * 32 + lane];
                float4 t1 = T4[(16 + ((p >> 4) & 15)) * 32 + lane];
                float4 t2 = T4[(32 + ((p >> 8) & 15)) * 32 + lane];
                float4 t3 = T4[(48 + ((p >> 12) & 3)) * 32 + lane];
                acc.x += a * (t0.x + t1.x + t2.x + t3.x);
                acc.y += a * (t0.y + t1.y + t2.y + t3.y);
                acc.z += a * (t0.z + t1.z + t2.z + t3.z);
                acc.w += a * (t0.w + t1.w + t2.w + t3.w);
            }
        }

        // ---- node output: node_fts + agg ----
        float4 nf = __ldg(((const float4*)emb_v) + (2 * nc) * 32 + lane);
        float4 no = make_float4(acc.x + nf.x, acc.y + nf.y, acc.z + nf.z, acc.w + nf.w);
        __stcs(((float4*)out_node) + n * 32 + lane, no);

        // ---- edge outputs: emb_e[ec] + agg, written directly per edge ----
#pragma unroll 2
        for (int i = 1; i < A; i++) {
            int p = sPk[warp][i];
            int e = sEid[warp][i];
            float4 t = T4[(52 + ((p >> 4) & 15)) * 32 + lane];
            float4 o = make_float4(acc.x + t.x, acc.y + t.y, acc.z + t.z, acc.w + t.w);
            __stcs(((float4*)out_edge) + (size_t)e * 32 + lane, o);
        }
    }
}

// ------------------------ host launch ----------------------------------------
extern "C" void kernel_launch(void* const* d_in, const int* in_sizes, int n_in,
                              void* d_out, int out_size) {
    const int*   node_states = (const int*)d_in[0];
    const int*   edge_states = (const int*)d_in[1];
    const float* scalars     = (const float*)d_in[2];
    const int*   src         = (const int*)d_in[3];
    const int*   dst         = (const int*)d_in[4];
    const int*   rev         = (const int*)d_in[5];
    const int*   slot        = (const int*)d_in[6];
    // d_in[7] = self_loop_idx (identity, unused)

    int w = 8;
    if (w < n_in && in_sizes[w] == 1) w++;   // skip max_deg scalar if present
    const float* emb_v = (const float*)d_in[w + 0];
    const float* emb_b = (const float*)d_in[w + 1];
    const float* emb_e = (const float*)d_in[w + 2];
    const float* emb_s = (const float*)d_in[w + 3];
    const float* Wq    = (const float*)d_in[w + 4];
    const float* Wk    = (const float*)d_in[w + 5];
    const float* Wv    = (const float*)d_in[w + 6];
    const float* Wek   = (const float*)d_in[w + 7];
    const float* Wev   = (const float*)d_in[w + 8];
    const float* Wcf   = (const float*)d_in[w + 9];
    const float* gW1   = (const float*)d_in[w + 10];
    const float* gb1   = (const float*)d_in[w + 11];
    const float* gW2   = (const float*)d_in[w + 12];
    const float* gb2   = (const float*)d_in[w + 13];

    float* out_node = (float*)d_out;
    float* out_edge = (float*)d_out + (size_t)N_NODES * 128;

    k_init<<<(N_EDGES + 255) / 256, 256>>>(node_states, edge_states);
    k_pre1<<<8, 128>>>(emb_v, emb_b, emb_e, emb_s, Wq, Wk, Wv, Wek, gW1, gb1, Wcf);
    k_pre2<<<4, 128>>>(Wev, gW2, gb2);
    k_pack<<<(N_EDGES / 2 + 255) / 256, 256>>>(src, dst, rev, slot, scalars);
    k_attn<<<ATTN_BLOCKS, 512>>>(emb_v, emb_e, out_node, out_edge);
}

// round 12
// speedup vs baseline: 1.8729x; 1.0430x over previous
#include <cuda_runtime.h>
#include <cstdint>

#define N_NODES 20000
#define N_EDGES 340000
#define DENSE_STRIDE 64
#define ATTN_BLOCKS 296        // 148 SMs * 2 resident blocks
#define N_WARPS (ATTN_BLOCKS * 16)
#define FULLMASK 0xffffffffu

// ----------------------------- device scratch -------------------------------
__device__ unsigned char      g_ncode[N_NODES];
__device__ unsigned char      g_ecode[N_EDGES];
__device__ int                g_deg[N_NODES];
__device__ unsigned long long g_dense64[N_NODES * DENSE_STRIDE]; // lo32=eid, hi16=pk; no clear

__device__ __align__(16) float g_Qt[2048], g_Kt[2048], g_Vt[2048], g_EKt[2048];
__device__ __align__(16) float g_H1[2048], g_T1[2048], g_T2[2048], g_T3[512];
__device__ __align__(16) float g_Ve1[2048], g_Ve2[2048], g_Vs[512];
__device__ float g_L[256], g_Lself[16], g_u[16];

// ----------------------------- helpers --------------------------------------
__device__ __forceinline__ float wredsum(float v) {
#pragma unroll
    for (int o = 16; o; o >>= 1) v += __shfl_xor_sync(FULLMASK, v, o);
    return v;
}
__device__ __forceinline__ int wredsumi(int v) {
#pragma unroll
    for (int o = 16; o; o >>= 1) v += __shfl_xor_sync(FULLMASK, v, o);
    return v;
}
__device__ __forceinline__ float wredmax(float v) {
#pragma unroll
    for (int o = 16; o; o >>= 1) v = fmaxf(v, __shfl_xor_sync(FULLMASK, v, o));
    return v;
}
__device__ __forceinline__ float iscan(float v, int lane) {
#pragma unroll
    for (int d = 1; d < 32; d <<= 1) {
        float t = __shfl_up_sync(FULLMASK, v, d);
        if (lane >= d) v += t;
    }
    return v;
}
__device__ __forceinline__ void cas(float& v, bool asc, int j, int lane) {
    float pv = __shfl_xor_sync(FULLMASK, v, j);
    bool keepmin = (((lane & j) == 0) == asc);
    v = keepmin ? fminf(v, pv) : fmaxf(v, pv);
}

// ------------------------ init: codes + deg reset ----------------------------
__global__ void k_init(const int* __restrict__ node_states,
                       const int* __restrict__ edge_states) {
    int i = blockIdx.x * blockDim.x + threadIdx.x;
    if (i < N_EDGES) {
        int c = edge_states[i * 4 + 0] + 2 * edge_states[i * 4 + 1] +
                4 * edge_states[i * 4 + 2] + 8 * edge_states[i * 4 + 3];
        g_ecode[i] = (unsigned char)c;
    }
    if (i < N_NODES) {
        int c = node_states[i * 4 + 0] + 2 * node_states[i * 4 + 1] +
                4 * node_states[i * 4 + 2] + 8 * node_states[i * 4 + 3];
        g_ncode[i] = (unsigned char)c;
        g_deg[i] = 0;
    }
}

// ------------------------ precompute stage 1 ---------------------------------
__global__ void k_pre1(const float* __restrict__ emb_v, const float* __restrict__ emb_b,
                       const float* __restrict__ emb_e, const float* __restrict__ emb_s,
                       const float* __restrict__ Wq, const float* __restrict__ Wk,
                       const float* __restrict__ Wv, const float* __restrict__ Wek,
                       const float* __restrict__ gW1, const float* __restrict__ gb1,
                       const float* __restrict__ Wcf) {
    __shared__ float As[16 * 128];
    int t = threadIdx.x, b = blockIdx.x;
    const float* W = 0; float* out = 0; int rows = 16;
    const float* bias = 0; bool do_relu = false;
#pragma unroll
    for (int r = 0; r < 16; r++) As[r * 128 + t] = 0.f;
    switch (b) {
        case 0: for (int r = 0; r < 16; r++) As[r*128+t] = emb_v[2*r*128 + t];
                W = Wq;  out = g_Qt;  break;
        case 1: for (int r = 0; r < 16; r++) As[r*128+t] = emb_v[2*r*128 + t];
                W = Wk;  out = g_Kt;  break;
        case 2: for (int r = 0; r < 16; r++) As[r*128+t] = emb_v[2*r*128 + t];
                W = Wv;  out = g_Vt;  break;
        case 3: for (int r = 0; r < 16; r++) As[r*128+t] = emb_b[2*r*128 + t];
                W = Wek; out = g_EKt; break;
        case 4: for (int r = 0; r < 16; r++) As[r*128+t] = emb_v[2*r*128 + t];
                W = gW1; out = g_H1; bias = gb1; do_relu = true; break;
        case 5: for (int r = 0; r < 16; r++) As[r*128+t] = emb_e[r*128 + t];
                W = Wcf;               out = g_T1; break;
        case 6: for (int r = 0; r < 16; r++) As[r*128+t] = emb_e[r*128 + t];
                W = Wcf + 128 * 128;   out = g_T2; break;
        case 7: for (int r = 0; r < 4;  r++) As[r*128+t] = emb_s[r*128 + t];
                W = Wcf + 256 * 128;   out = g_T3; rows = 4; break;
    }
    __syncthreads();
    float acc[16];
#pragma unroll
    for (int r = 0; r < 16; r++) acc[r] = 0.f;
    for (int k = 0; k < 128; k++) {
        float w = W[k * 128 + t];
#pragma unroll
        for (int r = 0; r < 16; r++) acc[r] += As[r * 128 + k] * w;
    }
    for (int r = 0; r < rows; r++) {
        float v = acc[r];
        if (bias) v += bias[t];
        if (do_relu) v = fmaxf(v, 0.f);
        out[r * 128 + t] = v;
    }
}

// ------------------------ precompute stage 2 ---------------------------------
__global__ void k_pre2(const float* __restrict__ Wev,
                       const float* __restrict__ gW2, const float* __restrict__ gb2) {
    __shared__ float As[16 * 128];
    __shared__ float Bs[16 * 128];
    int t = threadIdx.x, b = blockIdx.x;
    if (b < 3) {
        const float* src = (b == 0) ? g_T1 : (b == 1) ? g_T2 : g_T3;
        int rows = (b == 2) ? 4 : 16;
        for (int r = 0; r < 16; r++) As[r * 128 + t] = (r < rows) ? src[r * 128 + t] : 0.f;
        __syncthreads();
        float acc[16];
#pragma unroll
        for (int r = 0; r < 16; r++) acc[r] = 0.f;
        for (int k = 0; k < 128; k++) {
            float w = Wev[k * 128 + t];
#pragma unroll
            for (int r = 0; r < 16; r++) acc[r] += As[r * 128 + k] * w;
        }
        float* out = (b == 0) ? g_Ve1 : (b == 1) ? g_Ve2 : g_Vs;
        for (int r = 0; r < rows; r++) out[r * 128 + t] = acc[r];
    } else {
        for (int r = 0; r < 16; r++) {
            As[r * 128 + t] = g_Qt[r * 128 + t];
            Bs[r * 128 + t] = g_Kt[r * 128 + t] + g_EKt[r * 128 + t];
        }
        __syncthreads();
        const float SH = 11.31370849898476f;   // sqrt(128)
#pragma unroll
        for (int pi = 0; pi < 2; pi++) {
            int p = t + pi * 128;
            int qc = p >> 4, sc = p & 15;
            float a = 0.f;
            for (int k = 0; k < 128; k++) a += As[qc * 128 + k] * Bs[sc * 128 + k];
            g_L[p] = a / SH;
        }
        if (t < 16) {
            float a = 0.f;
            for (int k = 0; k < 128; k++) a += As[t * 128 + k] * g_Kt[t * 128 + k];
            g_Lself[t] = a / SH;
            float h = 0.f;
            for (int k = 0; k < 128; k++) h += g_H1[t * 128 + k] * gW2[k];
            h += gb2[0];
            g_u[t] = 1.0f / (1.0f + expf(-h));
        }
    }
}

// ------------------------ pack + scatter (1 edge/thread, fused 8B store) -----
__global__ void k_pack(const int* __restrict__ src, const int* __restrict__ dst,
                       const int* __restrict__ rev, const int* __restrict__ slot,
                       const float* __restrict__ scalars) {
    int e = blockIdx.x * blockDim.x + threadIdx.x;
    if (e >= N_EDGES) return;
    int s_ = __ldg(src + e), d_ = __ldg(dst + e);
    int r_ = __ldg(rev + e);
    int sl = __ldg(slot + e);
    float sv = __ldg(scalars + e);
    int sc = g_ncode[s_];
    int ec = g_ecode[e];
    int rc = g_ecode[r_];
    float rs = __ldg(scalars + d_);
    float ss = __ldg(scalars + s_);
    int rlx  = (sv < rs) ? 1 : 0;
    int rlxd = ((ss + sv) < rs) ? 1 : 0;
    int stc = rlx | (rlxd << 1);
    unsigned long long pk = (unsigned long long)(sc | (ec << 4) | (rc << 8) | (stc << 12));
    if (sl < DENSE_STRIDE - 1) {
        g_dense64[d_ * DENSE_STRIDE + sl] = (pk << 32) | (unsigned)e;
        atomicMax(&g_deg[d_], sl + 1);
    }
}

// ------------------------ fused attention + outputs --------------------------
// Persistent, STATIC per-warp schedule: warp w handles nodes w, w+N_WARPS, ...
// No barriers after the one-time table load; warps fully independent.
__global__ __launch_bounds__(512, 2) void k_attn(const float* __restrict__ emb_v,
                                                 const float* __restrict__ emb_e,
                                                 float* __restrict__ out_node,
                                                 float* __restrict__ out_edge) {
    // sTab rows: 0..15 Vt | 16..31 Ve1 | 32..47 Ve2 | 48..51 Vs | 52..67 EmbE
    __shared__ float sTab[68 * 128];
    __shared__ float sL[256];
    __shared__ float sLs[16];
    __shared__ float sU[16];
    __shared__ float sAtt[16][64];
    __shared__ unsigned long long sD[16][64];

    int tid = threadIdx.x;
    for (int i = tid; i < 68 * 128; i += 512) {
        int row = i >> 7, col = i & 127;
        float v;
        if      (row < 16) v = g_Vt[i];
        else if (row < 32) v = g_Ve1[(row - 16) * 128 + col];
        else if (row < 48) v = g_Ve2[(row - 32) * 128 + col];
        else if (row < 52) v = g_Vs[(row - 48) * 128 + col];
        else               v = emb_e[(row - 52) * 128 + col];
        sTab[i] = v;
    }
    if (tid < 256) sL[tid] = g_L[tid];
    if (tid < 16) { sLs[tid] = g_Lself[tid]; sU[tid] = g_u[tid]; }
    __syncthreads();                     // only block-wide sync in the kernel

    int warp = tid >> 5, lane = tid & 31;
    int gwarp = blockIdx.x * 16 + warp;
    const float4* T4 = (const float4*)sTab;

    for (int n = gwarp; n < N_NODES; n += N_WARPS) {
        int nc = g_ncode[n];
        int deg = g_deg[n];
        int A = deg + 1;                 // entry 0 = self
        int base = n * DENSE_STRIDE;
        int iA = base + (lane ? (lane - 1) : 0);
        int iB = base + lane + 31;

        // ---- gather entries (single 8B load each: lo32=eid, hi16=pk) ----
        const unsigned long long da = g_dense64[iA];
        const unsigned long long db = g_dense64[iB];
        int ca = (int)(da >> 32);
        int cb = (int)(db >> 32);
        bool actA = (lane == 0) || (lane - 1 < deg);
        bool actB = (lane + 31 < deg);
        float vA = (lane == 0) ? sLs[nc] : (actA ? sL[(nc << 4) | (ca & 15)] : -1e9f);
        float vB = actB ? sL[(nc << 4) | (cb & 15)] : -1e9f;
        float uu = sU[nc];
        bool lowU = (uu <= 0.5f);

        float attA = 0.f, attB = 0.f;

        if (A <= 32) {
            // ---- fast path: all entries in vA ----
            float psA = 0.f;
            if (lowU) {                   // softmax needed only for u <= 0.5
                float mx = wredmax(vA);
                float eAx = __expf(vA - mx);
                float S  = wredsum(eAx);
                psA = __fdividef(eAx, S);
            }

            float v = vA;
#pragma unroll
            for (int k = 2; k <= 32; k <<= 1) {
                bool asc = ((lane & k) == 0);
#pragma unroll
                for (int j = k >> 1; j; j >>= 1) cas(v, asc, j, lane);
            }
            float z = __shfl_sync(FULLMASK, v, lane ^ 31);     // descending

            float cz = iscan(z, lane);
            float q  = iscan(z * z, lane);
            float kf = (float)(lane + 1);
            float rk = __fdividef(1.0f, kf);
            float mz = cz * rk, mz2 = q * rk;
            float tc = mz - sqrtf(fmaxf(mz * mz - mz2 + rk, 0.f));

            int k15 = wredsumi(z > tc ? 1 : 0);
            float tau15 = __shfl_sync(FULLMASK, tc, k15 - 1);
            float r0 = fmaxf(vA - tau15, 0.f); float p15A = r0 * r0;

            float prA;
            if (lowU) {
                float w = uu * 2.0f;
                prA = (1.0f - w) * psA + w * p15A;
            } else {                      // sparsemax needed only for u > 0.5
                int ksp = wredsumi((kf * z > cz - 1.0f) ? 1 : 0);
                float csk = __shfl_sync(FULLMASK, cz, ksp - 1);
                float tausp = __fdividef(csk - 1.0f, (float)ksp);
                float pspA = fmaxf(vA - tausp, 0.f);
                float w = (uu - 0.5f) * 2.0f;
                prA = (1.0f - w) * p15A + w * pspA;
            }
            float selA = (prA > 1e-6f) ? 1.f : 0.f;
            float ssum = wredsum(selA) + 1e-9f;
            attA = ((selA / ssum) - prA) + prA;
            if (!actA) attA = 0.f;
        } else {
            // ---- full 64-entry path ----
            float psA = 0.f, psB = 0.f;
            if (lowU) {
                float mx = wredmax(fmaxf(vA, vB));
                float eAx = __expf(vA - mx), eBx = __expf(vB - mx);
                float S  = wredsum(eAx + eBx);
                psA = __fdividef(eAx, S); psB = __fdividef(eBx, S);
            }

            float v0 = vA, v1 = vB;
#pragma unroll
            for (int k = 2; k <= 32; k <<= 1) {
                bool a0 = ((lane & k) == 0);
                bool a1 = (k == 32) ? false : a0;
#pragma unroll
                for (int j = k >> 1; j; j >>= 1) { cas(v0, a0, j, lane); cas(v1, a1, j, lane); }
            }
            {
                float lo = fminf(v0, v1), hi = fmaxf(v0, v1); v0 = lo; v1 = hi;
#pragma unroll
                for (int j = 16; j; j >>= 1) { cas(v0, true, j, lane); cas(v1, true, j, lane); }
            }
            float z0 = __shfl_sync(FULLMASK, v1, lane ^ 31);
            float z1 = __shfl_sync(FULLMASK, v0, lane ^ 31);

            float cz0 = iscan(z0, lane);
            float tot = __shfl_sync(FULLMASK, cz0, 31);
            float cz1 = iscan(z1, lane) + tot;
            float q0  = iscan(z0 * z0, lane);
            float qt  = __shfl_sync(FULLMASK, q0, 31);
            float q1  = iscan(z1 * z1, lane) + qt;

            float kAf = (float)(lane + 1), kBf = (float)(lane + 33);
            float rkA = __fdividef(1.0f, kAf), rkB = __fdividef(1.0f, kBf);
            float mzA = cz0 * rkA, mz2A = q0 * rkA;
            float tcA = mzA - sqrtf(fmaxf(mzA * mzA - mz2A + rkA, 0.f));
            float mzB = cz1 * rkB, mz2B = q1 * rkB;
            float tcB = mzB - sqrtf(fmaxf(mzB * mzB - mz2B + rkB, 0.f));

            int k15 = wredsumi((z0 > tcA ? 1 : 0) + (z1 > tcB ? 1 : 0));
            int p15 = k15 - 1;
            float tA = __shfl_sync(FULLMASK, tcA, p15 & 31);
            float tB = __shfl_sync(FULLMASK, tcB, p15 & 31);
            float tau15 = (p15 < 32) ? tA : tB;
            float r0 = fmaxf(vA - tau15, 0.f); float p15A = r0 * r0;
            float r1 = fmaxf(vB - tau15, 0.f); float p15B = r1 * r1;

            float prA, prB;
            if (lowU) {
                float w = uu * 2.0f;
                prA = (1.0f - w) * psA + w * p15A;
                prB = (1.0f - w) * psB + w * p15B;
            } else {
                int ksp = wredsumi(((kAf * z0 > cz0 - 1.0f) ? 1 : 0) + ((kBf * z1 > cz1 - 1.0f) ? 1 : 0));
                int psp = ksp - 1;
                float cA = __shfl_sync(FULLMASK, cz0, psp & 31);
                float cB = __shfl_sync(FULLMASK, cz1, psp & 31);
                float csk = (psp < 32) ? cA : cB;
                float tausp = __fdividef(csk - 1.0f, (float)ksp);
                float pspA = fmaxf(vA - tausp, 0.f);
                float pspB = fmaxf(vB - tausp, 0.f);
                float w = (uu - 0.5f) * 2.0f;
                prA = (1.0f - w) * p15A + w * pspA;
                prB = (1.0f - w) * p15B + w * pspB;
            }
            float selA = (prA > 1e-6f) ? 1.f : 0.f;
            float selB = (prB > 1e-6f) ? 1.f : 0.f;
            float ssum = wredsum(selA + selB) + 1e-9f;
            attA = ((selA / ssum) - prA) + prA; if (!actA) attA = 0.f;
            attB = ((selB / ssum) - prB) + prB; if (!actB) attB = 0.f;
        }

        // ---- stage per-entry data (warp-private; only __syncwarp needed) ----
        sAtt[warp][lane] = attA;  sAtt[warp][lane + 32] = attB;
        sD[warp][lane]   = da;    sD[warp][lane + 32]   = db;
        __syncwarp();

        // ---- aggregate (lane owns columns 4*lane..4*lane+3) ----
        float a0 = sAtt[warp][0];
        float4 acc = make_float4(0.f, 0.f, 0.f, 0.f);
        if (a0 != 0.f) {
            float4 t = T4[nc * 32 + lane];
            acc.x = a0 * t.x; acc.y = a0 * t.y; acc.z = a0 * t.z; acc.w = a0 * t.w;
        }
#pragma unroll 2
        for (int i = 1; i < A; i++) {
            float a = sAtt[warp][i];
            if (a != 0.f) {
                int p = (int)(sD[warp][i] >> 32);
                float4 t0 = T4[(p & 15) * 32 + lane];
                float4 t1 = T4[(16 + ((p >> 4) & 15)) * 32 + lane];
                float4 t2 = T4[(32 + ((p >> 8) & 15)) * 32 + lane];
                float4 t3 = T4[(48 + ((p >> 12) & 3)) * 32 + lane];
                acc.x += a * (t0.x + t1.x + t2.x + t3.x);
                acc.y += a * (t0.y + t1.y + t2.y + t3.y);
                acc.z += a * (t0.z + t1.z + t2.z + t3.z);
                acc.w += a * (t0.w + t1.w + t2.w + t3.w);
            }
        }

        // ---- node output: node_fts + agg ----
        float4 nf = __ldg(((const float4*)emb_v) + (2 * nc) * 32 + lane);
        float4 no = make_float4(acc.x + nf.x, acc.y + nf.y, acc.z + nf.z, acc.w + nf.w);
        __stcs(((float4*)out_node) + n * 32 + lane, no);

        // ---- edge outputs: emb_e[ec] + agg, written directly per edge ----
#pragma unroll 2
        for (int i = 1; i < A; i++) {
            unsigned long long d = sD[warp][i];
            int p = (int)(d >> 32);
            int e = (int)(d & 0xffffffffull);
            float4 t = T4[(52 + ((p >> 4) & 15)) * 32 + lane];
            float4 o = make_float4(acc.x + t.x, acc.y + t.y, acc.z + t.z, acc.w + t.w);
            __stcs(((float4*)out_edge) + (size_t)e * 32 + lane, o);
        }
    }
}

// ------------------------ host launch ----------------------------------------
extern "C" void kernel_launch(void* const* d_in, const int* in_sizes, int n_in,
                              void* d_out, int out_size) {
    const int*   node_states = (const int*)d_in[0];
    const int*   edge_states = (const int*)d_in[1];
    const float* scalars     = (const float*)d_in[2];
    const int*   src         = (const int*)d_in[3];
    const int*   dst         = (const int*)d_in[4];
    const int*   rev         = (const int*)d_in[5];
    const int*   slot        = (const int*)d_in[6];
    // d_in[7] = self_loop_idx (identity, unused)

    int w = 8;
    if (w < n_in && in_sizes[w] == 1) w++;   // skip max_deg scalar if present
    const float* emb_v = (const float*)d_in[w + 0];
    const float* emb_b = (const float*)d_in[w + 1];
    const float* emb_e = (const float*)d_in[w + 2];
    const float* emb_s = (const float*)d_in[w + 3];
    const float* Wq    = (const float*)d_in[w + 4];
    const float* Wk    = (const float*)d_in[w + 5];
    const float* Wv    = (const float*)d_in[w + 6];
    const float* Wek   = (const float*)d_in[w + 7];
    const float* Wev   = (const float*)d_in[w + 8];
    const float* Wcf   = (const float*)d_in[w + 9];
    const float* gW1   = (const float*)d_in[w + 10];
    const float* gb1   = (const float*)d_in[w + 11];
    const float* gW2   = (const float*)d_in[w + 12];
    const float* gb2   = (const float*)d_in[w + 13];

    float* out_node = (float*)d_out;
    float* out_edge = (float*)d_out + (size_t)N_NODES * 128;

    k_init<<<(N_EDGES + 255) / 256, 256>>>(node_states, edge_states);
    k_pre1<<<8, 128>>>(emb_v, emb_b, emb_e, emb_s, Wq, Wk, Wv, Wek, gW1, gb1, Wcf);
    k_pre2<<<4, 128>>>(Wev, gW2, gb2);
    k_pack<<<(N_EDGES + 255) / 256, 256>>>(src, dst, rev, slot, scalars);
    k_attn<<<ATTN_BLOCKS, 512>>>(emb_v, emb_e, out_node, out_edge);
}

// round 13
// speedup vs baseline: 1.9091x; 1.0193x over previous
#include <cuda_runtime.h>
#include <cstdint>

#define N_NODES 20000
#define N_EDGES 340000
#define DENSE_STRIDE 64
#define ATTN_BLOCKS 296        // 148 SMs * 2 resident blocks
#define N_WARPS (ATTN_BLOCKS * 16)
#define FULLMASK 0xffffffffu
#define STAB_ROWS 112          // 0..15 Vt | 16..31 Ve1 | 32..95 VeS | 96..111 EmbE
#define STAB_BYTES (STAB_ROWS * 128 * 4)

// ----------------------------- device scratch -------------------------------
__device__ unsigned char      g_ncode[N_NODES];
__device__ unsigned char      g_ecode[N_EDGES];
__device__ int                g_deg[N_NODES];
__device__ unsigned long long g_dense64[N_NODES * DENSE_STRIDE]; // lo32=eid, hi16=pk; no clear

__device__ __align__(16) float g_Qt[2048], g_Kt[2048], g_Vt[2048], g_EKt[2048];
__device__ __align__(16) float g_H1[2048], g_T1[2048], g_T2[2048], g_T3[512];
__device__ __align__(16) float g_Ve1[2048], g_Ve2[2048], g_Vs[512];
__device__ float g_L[256], g_Lself[16], g_u[16];

// ----------------------------- helpers --------------------------------------
__device__ __forceinline__ float wredsum(float v) {
#pragma unroll
    for (int o = 16; o; o >>= 1) v += __shfl_xor_sync(FULLMASK, v, o);
    return v;
}
__device__ __forceinline__ int wredsumi(int v) {
#pragma unroll
    for (int o = 16; o; o >>= 1) v += __shfl_xor_sync(FULLMASK, v, o);
    return v;
}
__device__ __forceinline__ float wredmax(float v) {
#pragma unroll
    for (int o = 16; o; o >>= 1) v = fmaxf(v, __shfl_xor_sync(FULLMASK, v, o));
    return v;
}
__device__ __forceinline__ float iscan(float v, int lane) {
#pragma unroll
    for (int d = 1; d < 32; d <<= 1) {
        float t = __shfl_up_sync(FULLMASK, v, d);
        if (lane >= d) v += t;
    }
    return v;
}
__device__ __forceinline__ void cas(float& v, bool asc, int j, int lane) {
    float pv = __shfl_xor_sync(FULLMASK, v, j);
    bool keepmin = (((lane & j) == 0) == asc);
    v = keepmin ? fminf(v, pv) : fmaxf(v, pv);
}

// ------------------------ init: codes + deg reset ----------------------------
__global__ void k_init(const int* __restrict__ node_states,
                       const int* __restrict__ edge_states) {
    int i = blockIdx.x * blockDim.x + threadIdx.x;
    if (i < N_EDGES) {
        int c = edge_states[i * 4 + 0] + 2 * edge_states[i * 4 + 1] +
                4 * edge_states[i * 4 + 2] + 8 * edge_states[i * 4 + 3];
        g_ecode[i] = (unsigned char)c;
    }
    if (i < N_NODES) {
        int c = node_states[i * 4 + 0] + 2 * node_states[i * 4 + 1] +
                4 * node_states[i * 4 + 2] + 8 * node_states[i * 4 + 3];
        g_ncode[i] = (unsigned char)c;
        g_deg[i] = 0;
    }
}

// ------------------------ precompute stage 1 ---------------------------------
__global__ void k_pre1(const float* __restrict__ emb_v, const float* __restrict__ emb_b,
                       const float* __restrict__ emb_e, const float* __restrict__ emb_s,
                       const float* __restrict__ Wq, const float* __restrict__ Wk,
                       const float* __restrict__ Wv, const float* __restrict__ Wek,
                       const float* __restrict__ gW1, const float* __restrict__ gb1,
                       const float* __restrict__ Wcf) {
    __shared__ float As[16 * 128];
    int t = threadIdx.x, b = blockIdx.x;
    const float* W = 0; float* out = 0; int rows = 16;
    const float* bias = 0; bool do_relu = false;
#pragma unroll
    for (int r = 0; r < 16; r++) As[r * 128 + t] = 0.f;
    switch (b) {
        case 0: for (int r = 0; r < 16; r++) As[r*128+t] = emb_v[2*r*128 + t];
                W = Wq;  out = g_Qt;  break;
        case 1: for (int r = 0; r < 16; r++) As[r*128+t] = emb_v[2*r*128 + t];
                W = Wk;  out = g_Kt;  break;
        case 2: for (int r = 0; r < 16; r++) As[r*128+t] = emb_v[2*r*128 + t];
                W = Wv;  out = g_Vt;  break;
        case 3: for (int r = 0; r < 16; r++) As[r*128+t] = emb_b[2*r*128 + t];
                W = Wek; out = g_EKt; break;
        case 4: for (int r = 0; r < 16; r++) As[r*128+t] = emb_v[2*r*128 + t];
                W = gW1; out = g_H1; bias = gb1; do_relu = true; break;
        case 5: for (int r = 0; r < 16; r++) As[r*128+t] = emb_e[r*128 + t];
                W = Wcf;               out = g_T1; break;
        case 6: for (int r = 0; r < 16; r++) As[r*128+t] = emb_e[r*128 + t];
                W = Wcf + 128 * 128;   out = g_T2; break;
        case 7: for (int r = 0; r < 4;  r++) As[r*128+t] = emb_s[r*128 + t];
                W = Wcf + 256 * 128;   out = g_T3; rows = 4; break;
    }
    __syncthreads();
    float acc[16];
#pragma unroll
    for (int r = 0; r < 16; r++) acc[r] = 0.f;
    for (int k = 0; k < 128; k++) {
        float w = W[k * 128 + t];
#pragma unroll
        for (int r = 0; r < 16; r++) acc[r] += As[r * 128 + k] * w;
    }
    for (int r = 0; r < rows; r++) {
        float v = acc[r];
        if (bias) v += bias[t];
        if (do_relu) v = fmaxf(v, 0.f);
        out[r * 128 + t] = v;
    }
}

// ------------------------ precompute stage 2 ---------------------------------
__global__ void k_pre2(const float* __restrict__ Wev,
                       const float* __restrict__ gW2, const float* __restrict__ gb2) {
    __shared__ float As[16 * 128];
    __shared__ float Bs[16 * 128];
    int t = threadIdx.x, b = blockIdx.x;
    if (b < 3) {
        const float* src = (b == 0) ? g_T1 : (b == 1) ? g_T2 : g_T3;
        int rows = (b == 2) ? 4 : 16;
        for (int r = 0; r < 16; r++) As[r * 128 + t] = (r < rows) ? src[r * 128 + t] : 0.f;
        __syncthreads();
        float acc[16];
#pragma unroll
        for (int r = 0; r < 16; r++) acc[r] = 0.f;
        for (int k = 0; k < 128; k++) {
            float w = Wev[k * 128 + t];
#pragma unroll
            for (int r = 0; r < 16; r++) acc[r] += As[r * 128 + k] * w;
        }
        float* out = (b == 0) ? g_Ve1 : (b == 1) ? g_Ve2 : g_Vs;
        for (int r = 0; r < rows; r++) out[r * 128 + t] = acc[r];
    } else {
        for (int r = 0; r < 16; r++) {
            As[r * 128 + t] = g_Qt[r * 128 + t];
            Bs[r * 128 + t] = g_Kt[r * 128 + t] + g_EKt[r * 128 + t];
        }
        __syncthreads();
        const float SH = 11.31370849898476f;   // sqrt(128)
#pragma unroll
        for (int pi = 0; pi < 2; pi++) {
            int p = t + pi * 128;
            int qc = p >> 4, sc = p & 15;
            float a = 0.f;
            for (int k = 0; k < 128; k++) a += As[qc * 128 + k] * Bs[sc * 128 + k];
            g_L[p] = a / SH;
        }
        if (t < 16) {
            float a = 0.f;
            for (int k = 0; k < 128; k++) a += As[t * 128 + k] * g_Kt[t * 128 + k];
            g_Lself[t] = a / SH;
            float h = 0.f;
            for (int k = 0; k < 128; k++) h += g_H1[t * 128 + k] * gW2[k];
            h += gb2[0];
            g_u[t] = 1.0f / (1.0f + expf(-h));
        }
    }
}

// ------------------------ pack + scatter (1 edge/thread, fused 8B store) -----
__global__ void k_pack(const int* __restrict__ src, const int* __restrict__ dst,
                       const int* __restrict__ rev, const int* __restrict__ slot,
                       const float* __restrict__ scalars) {
    int e = blockIdx.x * blockDim.x + threadIdx.x;
    if (e >= N_EDGES) return;
    int s_ = __ldg(src + e), d_ = __ldg(dst + e);
    int r_ = __ldg(rev + e);
    int sl = __ldg(slot + e);
    float sv = __ldg(scalars + e);
    int sc = g_ncode[s_];
    int ec = g_ecode[e];
    int rc = g_ecode[r_];
    float rs = __ldg(scalars + d_);
    float ss = __ldg(scalars + s_);
    int rlx  = (sv < rs) ? 1 : 0;
    int rlxd = ((ss + sv) < rs) ? 1 : 0;
    int stc = rlx | (rlxd << 1);
    unsigned long long pk = (unsigned long long)(sc | (ec << 4) | (rc << 8) | (stc << 12));
    if (sl < DENSE_STRIDE - 1) {
        g_dense64[d_ * DENSE_STRIDE + sl] = (pk << 32) | (unsigned)e;
        atomicMax(&g_deg[d_], sl + 1);
    }
}

// ------------------------ fused attention + outputs --------------------------
// Persistent, STATIC per-warp schedule: warp w handles nodes w, w+N_WARPS, ...
// sTab in dynamic smem; VeS = Ve2[rc] + Vs[stc] precombined (64 rows).
__global__ __launch_bounds__(512, 2) void k_attn(const float* __restrict__ emb_v,
                                                 const float* __restrict__ emb_e,
                                                 float* __restrict__ out_node,
                                                 float* __restrict__ out_edge) {
    extern __shared__ float sTab[];     // STAB_ROWS * 128 floats
    __shared__ float sL[256];
    __shared__ float sLs[16];
    __shared__ float sU[16];
    __shared__ float sAtt[16][64];
    __shared__ unsigned long long sD[16][64];

    int tid = threadIdx.x;
    for (int i = tid; i < STAB_ROWS * 128; i += 512) {
        int row = i >> 7, col = i & 127;
        float v;
        if      (row < 16) v = g_Vt[i];
        else if (row < 32) v = g_Ve1[(row - 16) * 128 + col];
        else if (row < 96) {
            int r = row - 32;            // r = rc + 16*stc
            v = g_Ve2[(r & 15) * 128 + col] + g_Vs[(r >> 4) * 128 + col];
        }
        else               v = emb_e[(row - 96) * 128 + col];
        sTab[i] = v;
    }
    if (tid < 256) sL[tid] = g_L[tid];
    if (tid < 16) { sLs[tid] = g_Lself[tid]; sU[tid] = g_u[tid]; }
    __syncthreads();                     // only block-wide sync in the kernel

    int warp = tid >> 5, lane = tid & 31;
    int gwarp = blockIdx.x * 16 + warp;
    const float4* T4 = (const float4*)sTab;

    for (int n = gwarp; n < N_NODES; n += N_WARPS) {
        int nc = g_ncode[n];
        int deg = g_deg[n];
        int A = deg + 1;                 // entry 0 = self
        int base = n * DENSE_STRIDE;
        int iA = base + (lane ? (lane - 1) : 0);
        int iB = base + lane + 31;

        // ---- gather entries (single 8B load each: lo32=eid, hi16=pk) ----
        const unsigned long long da = g_dense64[iA];
        const unsigned long long db = g_dense64[iB];
        int ca = (int)(da >> 32);
        int cb = (int)(db >> 32);
        bool actA = (lane == 0) || (lane - 1 < deg);
        bool actB = (lane + 31 < deg);
        float vA = (lane == 0) ? sLs[nc] : (actA ? sL[(nc << 4) | (ca & 15)] : -1e9f);
        float vB = actB ? sL[(nc << 4) | (cb & 15)] : -1e9f;
        float uu = sU[nc];
        bool lowU = (uu <= 0.5f);

        float attA = 0.f, attB = 0.f;

        if (A <= 32) {
            // ---- fast path: all entries in vA ----
            float psA = 0.f;
            if (lowU) {                   // softmax needed only for u <= 0.5
                float mx = wredmax(vA);
                float eAx = __expf(vA - mx);
                float S  = wredsum(eAx);
                psA = __fdividef(eAx, S);
            }

            float v = vA;
#pragma unroll
            for (int k = 2; k <= 32; k <<= 1) {
                bool asc = ((lane & k) == 0);
#pragma unroll
                for (int j = k >> 1; j; j >>= 1) cas(v, asc, j, lane);
            }
            float z = __shfl_sync(FULLMASK, v, lane ^ 31);     // descending

            float cz = iscan(z, lane);
            float q  = iscan(z * z, lane);
            float kf = (float)(lane + 1);
            float rk = __fdividef(1.0f, kf);
            float mz = cz * rk, mz2 = q * rk;
            float tc = mz - sqrtf(fmaxf(mz * mz - mz2 + rk, 0.f));

            int k15 = wredsumi(z > tc ? 1 : 0);
            float tau15 = __shfl_sync(FULLMASK, tc, k15 - 1);
            float r0 = fmaxf(vA - tau15, 0.f); float p15A = r0 * r0;

            float prA;
            if (lowU) {
                float w = uu * 2.0f;
                prA = (1.0f - w) * psA + w * p15A;
            } else {                      // sparsemax needed only for u > 0.5
                int ksp = wredsumi((kf * z > cz - 1.0f) ? 1 : 0);
                float csk = __shfl_sync(FULLMASK, cz, ksp - 1);
                float tausp = __fdividef(csk - 1.0f, (float)ksp);
                float pspA = fmaxf(vA - tausp, 0.f);
                float w = (uu - 0.5f) * 2.0f;
                prA = (1.0f - w) * p15A + w * pspA;
            }
            float selA = (prA > 1e-6f) ? 1.f : 0.f;
            float ssum = wredsum(selA) + 1e-9f;
            attA = ((selA / ssum) - prA) + prA;
            if (!actA) attA = 0.f;
        } else {
            // ---- full 64-entry path ----
            float psA = 0.f, psB = 0.f;
            if (lowU) {
                float mx = wredmax(fmaxf(vA, vB));
                float eAx = __expf(vA - mx), eBx = __expf(vB - mx);
                float S  = wredsum(eAx + eBx);
                psA = __fdividef(eAx, S); psB = __fdividef(eBx, S);
            }

            float v0 = vA, v1 = vB;
#pragma unroll
            for (int k = 2; k <= 32; k <<= 1) {
                bool a0 = ((lane & k) == 0);
                bool a1 = (k == 32) ? false : a0;
#pragma unroll
                for (int j = k >> 1; j; j >>= 1) { cas(v0, a0, j, lane); cas(v1, a1, j, lane); }
            }
            {
                float lo = fminf(v0, v1), hi = fmaxf(v0, v1); v0 = lo; v1 = hi;
#pragma unroll
                for (int j = 16; j; j >>= 1) { cas(v0, true, j, lane); cas(v1, true, j, lane); }
            }
            float z0 = __shfl_sync(FULLMASK, v1, lane ^ 31);
            float z1 = __shfl_sync(FULLMASK, v0, lane ^ 31);

            float cz0 = iscan(z0, lane);
            float tot = __shfl_sync(FULLMASK, cz0, 31);
            float cz1 = iscan(z1, lane) + tot;
            float q0  = iscan(z0 * z0, lane);
            float qt  = __shfl_sync(FULLMASK, q0, 31);
            float q1  = iscan(z1 * z1, lane) + qt;

            float kAf = (float)(lane + 1), kBf = (float)(lane + 33);
            float rkA = __fdividef(1.0f, kAf), rkB = __fdividef(1.0f, kBf);
            float mzA = cz0 * rkA, mz2A = q0 * rkA;
            float tcA = mzA - sqrtf(fmaxf(mzA * mzA - mz2A + rkA, 0.f));
            float mzB = cz1 * rkB, mz2B = q1 * rkB;
            float tcB = mzB - sqrtf(fmaxf(mzB * mzB - mz2B + rkB, 0.f));

            int k15 = wredsumi((z0 > tcA ? 1 : 0) + (z1 > tcB ? 1 : 0));
            int p15 = k15 - 1;
            float tA = __shfl_sync(FULLMASK, tcA, p15 & 31);
            float tB = __shfl_sync(FULLMASK, tcB, p15 & 31);
            float tau15 = (p15 < 32) ? tA : tB;
            float r0 = fmaxf(vA - tau15, 0.f); float p15A = r0 * r0;
            float r1 = fmaxf(vB - tau15, 0.f); float p15B = r1 * r1;

            float prA, prB;
            if (lowU) {
                float w = uu * 2.0f;
                prA = (1.0f - w) * psA + w * p15A;
                prB = (1.0f - w) * psB + w * p15B;
            } else {
                int ksp = wredsumi(((kAf * z0 > cz0 - 1.0f) ? 1 : 0) + ((kBf * z1 > cz1 - 1.0f) ? 1 : 0));
                int psp = ksp - 1;
                float cA = __shfl_sync(FULLMASK, cz0, psp & 31);
                float cB = __shfl_sync(FULLMASK, cz1, psp & 31);
                float csk = (psp < 32) ? cA : cB;
                float tausp = __fdividef(csk - 1.0f, (float)ksp);
                float pspA = fmaxf(vA - tausp, 0.f);
                float pspB = fmaxf(vB - tausp, 0.f);
                float w = (uu - 0.5f) * 2.0f;
                prA = (1.0f - w) * p15A + w * pspA;
                prB = (1.0f - w) * p15B + w * pspB;
            }
            float selA = (prA > 1e-6f) ? 1.f : 0.f;
            float selB = (prB > 1e-6f) ? 1.f : 0.f;
            float ssum = wredsum(selA + selB) + 1e-9f;
            attA = ((selA / ssum) - prA) + prA; if (!actA) attA = 0.f;
            attB = ((selB / ssum) - prB) + prB; if (!actB) attB = 0.f;
        }

        // ---- stage per-entry data (warp-private; only __syncwarp needed) ----
        sAtt[warp][lane] = attA;  sAtt[warp][lane + 32] = attB;
        sD[warp][lane]   = da;    sD[warp][lane + 32]   = db;
        __syncwarp();

        // ---- aggregate (lane owns columns 4*lane..4*lane+3); 3 lookups -----
        float a0 = sAtt[warp][0];
        float4 acc = make_float4(0.f, 0.f, 0.f, 0.f);
        if (a0 != 0.f) {
            float4 t = T4[nc * 32 + lane];
            acc.x = a0 * t.x; acc.y = a0 * t.y; acc.z = a0 * t.z; acc.w = a0 * t.w;
        }
#pragma unroll 2
        for (int i = 1; i < A; i++) {
            float a = sAtt[warp][i];
            if (a != 0.f) {
                int p = (int)(sD[warp][i] >> 32);
                float4 t0 = T4[(p & 15) * 32 + lane];
                float4 t1 = T4[(16 + ((p >> 4) & 15)) * 32 + lane];
                float4 t2 = T4[(32 + ((p >> 8) & 63)) * 32 + lane];   // VeS = Ve2+Vs
                acc.x += a * (t0.x + t1.x + t2.x);
                acc.y += a * (t0.y + t1.y + t2.y);
                acc.z += a * (t0.z + t1.z + t2.z);
                acc.w += a * (t0.w + t1.w + t2.w);
            }
        }

        // ---- node output: node_fts + agg ----
        float4 nf = __ldg(((const float4*)emb_v) + (2 * nc) * 32 + lane);
        float4 no = make_float4(acc.x + nf.x, acc.y + nf.y, acc.z + nf.z, acc.w + nf.w);
        __stcs(((float4*)out_node) + n * 32 + lane, no);

        // ---- edge outputs: emb_e[ec] + agg, written directly per edge ----
#pragma unroll 2
        for (int i = 1; i < A; i++) {
            unsigned long long d = sD[warp][i];
            int p = (int)(d >> 32);
            int e = (int)(d & 0xffffffffull);
            float4 t = T4[(96 + ((p >> 4) & 15)) * 32 + lane];
            float4 o = make_float4(acc.x + t.x, acc.y + t.y, acc.z + t.z, acc.w + t.w);
            __stcs(((float4*)out_edge) + (size_t)e * 32 + lane, o);
        }
    }
}

// ------------------------ host launch ----------------------------------------
extern "C" void kernel_launch(void* const* d_in, const int* in_sizes, int n_in,
                              void* d_out, int out_size) {
    const int*   node_states = (const int*)d_in[0];
    const int*   edge_states = (const int*)d_in[1];
    const float* scalars     = (const float*)d_in[2];
    const int*   src         = (const int*)d_in[3];
    const int*   dst         = (const int*)d_in[4];
    const int*   rev         = (const int*)d_in[5];
    const int*   slot        = (const int*)d_in[6];
    // d_in[7] = self_loop_idx (identity, unused)

    int w = 8;
    if (w < n_in && in_sizes[w] == 1) w++;   // skip max_deg scalar if present
    const float* emb_v = (const float*)d_in[w + 0];
    const float* emb_b = (const float*)d_in[w + 1];
    const float* emb_e = (const float*)d_in[w + 2];
    const float* emb_s = (const float*)d_in[w + 3];
    const float* Wq    = (const float*)d_in[w + 4];
    const float* Wk    = (const float*)d_in[w + 5];
    const float* Wv    = (const float*)d_in[w + 6];
    const float* Wek   = (const float*)d_in[w + 7];
    const float* Wev   = (const float*)d_in[w + 8];
    const float* Wcf   = (const float*)d_in[w + 9];
    const float* gW1   = (const float*)d_in[w + 10];
    const float* gb1   = (const float*)d_in[w + 11];
    const float* gW2   = (const float*)d_in[w + 12];
    const float* gb2   = (const float*)d_in[w + 13];

    float* out_node = (float*)d_out;
    float* out_edge = (float*)d_out + (size_t)N_NODES * 128;

    static int smem_configured = 0;
    if (!smem_configured) {
        cudaFuncSetAttribute(k_attn, cudaFuncAttributeMaxDynamicSharedMemorySize, STAB_BYTES);
        smem_configured = 1;
    }

    k_init<<<(N_EDGES + 255) / 256, 256>>>(node_states, edge_states);
    k_pre1<<<8, 128>>>(emb_v, emb_b, emb_e, emb_s, Wq, Wk, Wv, Wek, gW1, gb1, Wcf);
    k_pre2<<<4, 128>>>(Wev, gW2, gb2);
    k_pack<<<(N_EDGES + 255) / 256, 256>>>(src, dst, rev, slot, scalars);
    k_attn<<<ATTN_BLOCKS, 512, STAB_BYTES>>>(emb_v, emb_e, out_node, out_edge);
}

// round 16
// speedup vs baseline: 2.2016x; 1.1532x over previous
#include <cuda_runtime.h>
#include <cstdint>

#define N_NODES 20000
#define N_EDGES 340000
#define DENSE_STRIDE 64
#define ATTN_BLOCKS 296        // 148 SMs * 2 resident blocks
#define N_WARPS (ATTN_BLOCKS * 16)
#define FULLMASK 0xffffffffu
#define STAB_ROWS 112          // 0..15 Vt | 16..31 Ve1 | 32..95 VeS | 96..111 EmbE
#define STAB_BYTES (STAB_ROWS * 128 * 4)

// ----------------------------- device scratch -------------------------------
__device__ unsigned char      g_ncode[N_NODES];
__device__ unsigned char      g_ecode[N_EDGES];
__device__ int                g_deg[N_NODES];
__device__ unsigned long long g_dense64[N_NODES * DENSE_STRIDE]; // lo32=eid, hi16=pk; no clear
__device__ int                g_preflag;

__device__ __align__(16) float g_Qt[2048], g_Kt[2048], g_Vt[2048], g_EKt[2048];
__device__ __align__(16) float g_H1[2048], g_T1[2048], g_T2[2048], g_T3[512];
__device__ __align__(16) float g_Ve1[2048], g_Ve2[2048], g_Vs[512];
__device__ float g_L[256], g_Lself[16], g_u[16];

// ----------------------------- helpers --------------------------------------
__device__ __forceinline__ float wredsum(float v) {
#pragma unroll
    for (int o = 16; o; o >>= 1) v += __shfl_xor_sync(FULLMASK, v, o);
    return v;
}
__device__ __forceinline__ int wredsumi(int v) {
#pragma unroll
    for (int o = 16; o; o >>= 1) v += __shfl_xor_sync(FULLMASK, v, o);
    return v;
}
__device__ __forceinline__ float wredmax(float v) {
#pragma unroll
    for (int o = 16; o; o >>= 1) v = fmaxf(v, __shfl_xor_sync(FULLMASK, v, o));
    return v;
}
__device__ __forceinline__ float iscan(float v, int lane) {
#pragma unroll
    for (int d = 1; d < 32; d <<= 1) {
        float t = __shfl_up_sync(FULLMASK, v, d);
        if (lane >= d) v += t;
    }
    return v;
}
__device__ __forceinline__ void cas(float& v, bool asc, int j, int lane) {
    float pv = __shfl_xor_sync(FULLMASK, v, j);
    bool keepmin = (((lane & j) == 0) == asc);
    v = keepmin ? fminf(v, pv) : fmaxf(v, pv);
}

// ------------------------ init: codes + deg + flag reset ---------------------
__global__ void k_init(const int* __restrict__ node_states,
                       const int* __restrict__ edge_states) {
    int i = blockIdx.x * blockDim.x + threadIdx.x;
    if (i < N_EDGES) {
        int c = edge_states[i * 4 + 0] + 2 * edge_states[i * 4 + 1] +
                4 * edge_states[i * 4 + 2] + 8 * edge_states[i * 4 + 3];
        g_ecode[i] = (unsigned char)c;
    }
    if (i < N_NODES) {
        int c = node_states[i * 4 + 0] + 2 * node_states[i * 4 + 1] +
                4 * node_states[i * 4 + 2] + 8 * node_states[i * 4 + 3];
        g_ncode[i] = (unsigned char)c;
        g_deg[i] = 0;
    }
    if (i == 0) g_preflag = 0;
}

// ------------------------ merged precompute (pre1 + pre2) --------------------
// Blocks 0-7: stage-1 mini-GEMMs, then publish via g_preflag.
// Blocks 8-11: spin until all 8 stage-1 blocks done, then stage-2.
// All 12 blocks are co-resident (148 SMs) -> no deadlock.
__global__ void k_pre(const float* __restrict__ emb_v, const float* __restrict__ emb_b,
                      const float* __restrict__ emb_e, const float* __restrict__ emb_s,
                      const float* __restrict__ Wq, const float* __restrict__ Wk,
                      const float* __restrict__ Wv, const float* __restrict__ Wek,
                      const float* __restrict__ gW1, const float* __restrict__ gb1,
                      const float* __restrict__ Wcf, const float* __restrict__ Wev,
                      const float* __restrict__ gW2, const float* __restrict__ gb2) {
    __shared__ float As[16 * 128];
    __shared__ float Bs[16 * 128];
    int t = threadIdx.x, b = blockIdx.x;

    if (b < 8) {
        const float* W = 0; float* out = 0; int rows = 16;
        const float* bias = 0; bool do_relu = false;
#pragma unroll
        for (int r = 0; r < 16; r++) As[r * 128 + t] = 0.f;
        switch (b) {
            case 0: for (int r = 0; r < 16; r++) As[r*128+t] = emb_v[2*r*128 + t];
                    W = Wq;  out = g_Qt;  break;
            case 1: for (int r = 0; r < 16; r++) As[r*128+t] = emb_v[2*r*128 + t];
                    W = Wk;  out = g_Kt;  break;
            case 2: for (int r = 0; r < 16; r++) As[r*128+t] = emb_v[2*r*128 + t];
                    W = Wv;  out = g_Vt;  break;
            case 3: for (int r = 0; r < 16; r++) As[r*128+t] = emb_b[2*r*128 + t];
                    W = Wek; out = g_EKt; break;
            case 4: for (int r = 0; r < 16; r++) As[r*128+t] = emb_v[2*r*128 + t];
                    W = gW1; out = g_H1; bias = gb1; do_relu = true; break;
            case 5: for (int r = 0; r < 16; r++) As[r*128+t] = emb_e[r*128 + t];
                    W = Wcf;               out = g_T1; break;
            case 6: for (int r = 0; r < 16; r++) As[r*128+t] = emb_e[r*128 + t];
                    W = Wcf + 128 * 128;   out = g_T2; break;
            case 7: for (int r = 0; r < 4;  r++) As[r*128+t] = emb_s[r*128 + t];
                    W = Wcf + 256 * 128;   out = g_T3; rows = 4; break;
        }
        __syncthreads();
        float acc[16];
#pragma unroll
        for (int r = 0; r < 16; r++) acc[r] = 0.f;
        for (int k = 0; k < 128; k++) {
            float w = W[k * 128 + t];
#pragma unroll
            for (int r = 0; r < 16; r++) acc[r] += As[r * 128 + k] * w;
        }
        for (int r = 0; r < rows; r++) {
            float v = acc[r];
            if (bias) v += bias[t];
            if (do_relu) v = fmaxf(v, 0.f);
            out[r * 128 + t] = v;
        }
        __threadfence();                 // publish all writes device-wide
        __syncthreads();
        if (t == 0) atomicAdd(&g_preflag, 1);
    } else {
        // wait for all stage-1 blocks
        if (t == 0) {
            while (atomicAdd(&g_preflag, 0) < 8) __nanosleep(50);
        }
        __syncthreads();
        __threadfence();                 // acquire

        int bb = b - 8;
        if (bb < 3) {
            const float* src = (bb == 0) ? g_T1 : (bb == 1) ? g_T2 : g_T3;
            int rows = (bb == 2) ? 4 : 16;
            for (int r = 0; r < 16; r++) As[r * 128 + t] = (r < rows) ? src[r * 128 + t] : 0.f;
            __syncthreads();
            float acc[16];
#pragma unroll
            for (int r = 0; r < 16; r++) acc[r] = 0.f;
            for (int k = 0; k < 128; k++) {
                float w = Wev[k * 128 + t];
#pragma unroll
                for (int r = 0; r < 16; r++) acc[r] += As[r * 128 + k] * w;
            }
            float* out = (bb == 0) ? g_Ve1 : (bb == 1) ? g_Ve2 : g_Vs;
            for (int r = 0; r < rows; r++) out[r * 128 + t] = acc[r];
        } else {
            for (int r = 0; r < 16; r++) {
                As[r * 128 + t] = g_Qt[r * 128 + t];
                Bs[r * 128 + t] = g_Kt[r * 128 + t] + g_EKt[r * 128 + t];
            }
            __syncthreads();
            const float SH = 11.31370849898476f;   // sqrt(128)
#pragma unroll
            for (int pi = 0; pi < 2; pi++) {
                int p = t + pi * 128;
                int qc = p >> 4, sc = p & 15;
                float a = 0.f;
                for (int k = 0; k < 128; k++) a += As[qc * 128 + k] * Bs[sc * 128 + k];
                g_L[p] = a / SH;
            }
            if (t < 16) {
                float a = 0.f;
                for (int k = 0; k < 128; k++) a += As[t * 128 + k] * g_Kt[t * 128 + k];
                g_Lself[t] = a / SH;
                float h = 0.f;
                for (int k = 0; k < 128; k++) h += g_H1[t * 128 + k] * gW2[k];
                h += gb2[0];
                g_u[t] = 1.0f / (1.0f + expf(-h));
            }
        }
    }
}

// ------------------------ pack + scatter (1 edge/thread, fused 8B store) -----
__global__ void k_pack(const int* __restrict__ src, const int* __restrict__ dst,
                       const int* __restrict__ rev, const int* __restrict__ slot,
                       const float* __restrict__ scalars) {
    int e = blockIdx.x * blockDim.x + threadIdx.x;
    if (e >= N_EDGES) return;
    int s_ = __ldg(src + e), d_ = __ldg(dst + e);
    int r_ = __ldg(rev + e);
    int sl = __ldg(slot + e);
    float sv = __ldg(scalars + e);
    int sc = g_ncode[s_];
    int ec = g_ecode[e];
    int rc = g_ecode[r_];
    float rs = __ldg(scalars + d_);
    float ss = __ldg(scalars + s_);
    int rlx  = (sv < rs) ? 1 : 0;
    int rlxd = ((ss + sv) < rs) ? 1 : 0;
    int stc = rlx | (rlxd << 1);
    unsigned long long pk = (unsigned long long)(sc | (ec << 4) | (rc << 8) | (stc << 12));
    if (sl < DENSE_STRIDE - 1) {
        g_dense64[d_ * DENSE_STRIDE + sl] = (pk << 32) | (unsigned)e;
        atomicMax(&g_deg[d_], sl + 1);
    }
}

// ------------------------ fused attention + outputs --------------------------
// Persistent, STATIC per-warp schedule with cross-iteration prefetch.
__global__ __launch_bounds__(512, 2) void k_attn(const float* __restrict__ emb_v,
                                                 const float* __restrict__ emb_e,
                                                 float* __restrict__ out_node,
                                                 float* __restrict__ out_edge) {
    extern __shared__ float sTab[];     // STAB_ROWS * 128 floats
    __shared__ float sL[256];
    __shared__ float sLs[16];
    __shared__ float sU[16];
    __shared__ float sAtt[16][64];
    __shared__ unsigned long long sD[16][64];

    int tid = threadIdx.x;
    for (int i = tid; i < STAB_ROWS * 128; i += 512) {
        int row = i >> 7, col = i & 127;
        float v;
        if      (row < 16) v = g_Vt[i];
        else if (row < 32) v = g_Ve1[(row - 16) * 128 + col];
        else if (row < 96) {
            int r = row - 32;            // r = rc + 16*stc
            v = g_Ve2[(r & 15) * 128 + col] + g_Vs[(r >> 4) * 128 + col];
        }
        else               v = emb_e[(row - 96) * 128 + col];
        sTab[i] = v;
    }
    if (tid < 256) sL[tid] = g_L[tid];
    if (tid < 16) { sLs[tid] = g_Lself[tid]; sU[tid] = g_u[tid]; }
    __syncthreads();                     // only block-wide sync in the kernel

    int warp = tid >> 5, lane = tid & 31;
    int gwarp = blockIdx.x * 16 + warp;
    const float4* T4 = (const float4*)sTab;
    int offA = lane ? (lane - 1) : 0;

    // ---- preload first node ----
    int n = gwarp;
    int nc = 0, deg = 0;
    unsigned long long da = 0, db = 0;
    if (n < N_NODES) {
        nc  = g_ncode[n];
        deg = g_deg[n];
        da  = g_dense64[n * DENSE_STRIDE + offA];
        db  = g_dense64[n * DENSE_STRIDE + lane + 31];
    }

    for (; n < N_NODES; ) {
        int nn = n + N_WARPS;
        // ---- prefetch next node's data (overlaps with this node's math) ----
        int nc2 = 0, deg2 = 0;
        unsigned long long da2 = 0, db2 = 0;
        if (nn < N_NODES) {
            nc2  = g_ncode[nn];
            deg2 = g_deg[nn];
            da2  = g_dense64[nn * DENSE_STRIDE + offA];
            db2  = g_dense64[nn * DENSE_STRIDE + lane + 31];
        }

        int A = deg + 1;                 // entry 0 = self
        int ca = (int)(da >> 32);
        int cb = (int)(db >> 32);
        bool actA = (lane == 0) || (lane - 1 < deg);
        bool actB = (lane + 31 < deg);
        float vA = (lane == 0) ? sLs[nc] : (actA ? sL[(nc << 4) | (ca & 15)] : -1e9f);
        float vB = actB ? sL[(nc << 4) | (cb & 15)] : -1e9f;
        float uu = sU[nc];
        bool lowU = (uu <= 0.5f);

        float attA = 0.f, attB = 0.f;

        if (A <= 32) {
            // ---- fast path: all entries in vA ----
            float psA = 0.f;
            if (lowU) {                   // softmax needed only for u <= 0.5
                float mx = wredmax(vA);
                float eAx = __expf(vA - mx);
                float S  = wredsum(eAx);
                psA = __fdividef(eAx, S);
            }

            float v = vA;
#pragma unroll
            for (int k = 2; k <= 32; k <<= 1) {
                bool asc = ((lane & k) == 0);
#pragma unroll
                for (int j = k >> 1; j; j >>= 1) cas(v, asc, j, lane);
            }
            float z = __shfl_sync(FULLMASK, v, lane ^ 31);     // descending

            float cz = iscan(z, lane);
            float q  = iscan(z * z, lane);
            float kf = (float)(lane + 1);
            float rk = __fdividef(1.0f, kf);
            float mz = cz * rk, mz2 = q * rk;
            float tc = mz - sqrtf(fmaxf(mz * mz - mz2 + rk, 0.f));

            int k15 = wredsumi(z > tc ? 1 : 0);
            float tau15 = __shfl_sync(FULLMASK, tc, k15 - 1);
            float r0 = fmaxf(vA - tau15, 0.f); float p15A = r0 * r0;

            float prA;
            if (lowU) {
                float w = uu * 2.0f;
                prA = (1.0f - w) * psA + w * p15A;
            } else {                      // sparsemax needed only for u > 0.5
                int ksp = wredsumi((kf * z > cz - 1.0f) ? 1 : 0);
                float csk = __shfl_sync(FULLMASK, cz, ksp - 1);
                float tausp = __fdividef(csk - 1.0f, (float)ksp);
                float pspA = fmaxf(vA - tausp, 0.f);
                float w = (uu - 0.5f) * 2.0f;
                prA = (1.0f - w) * p15A + w * pspA;
            }
            float selA = (prA > 1e-6f) ? 1.f : 0.f;
            float ssum = wredsum(selA) + 1e-9f;
            attA = ((selA / ssum) - prA) + prA;
            if (!actA) attA = 0.f;
        } else {
            // ---- full 64-entry path ----
            float psA = 0.f, psB = 0.f;
            if (lowU) {
                float mx = wredmax(fmaxf(vA, vB));
                float eAx = __expf(vA - mx), eBx = __expf(vB - mx);
                float S  = wredsum(eAx + eBx);
                psA = __fdividef(eAx, S); psB = __fdividef(eBx, S);
            }

            float v0 = vA, v1 = vB;
#pragma unroll
            for (int k = 2; k <= 32; k <<= 1) {
                bool a0 = ((lane & k) == 0);
                bool a1 = (k == 32) ? false : a0;
#pragma unroll
                for (int j = k >> 1; j; j >>= 1) { cas(v0, a0, j, lane); cas(v1, a1, j, lane); }
            }
            {
                float lo = fminf(v0, v1), hi = fmaxf(v0, v1); v0 = lo; v1 = hi;
#pragma unroll
                for (int j = 16; j; j >>= 1) { cas(v0, true, j, lane); cas(v1, true, j, lane); }
            }
            float z0 = __shfl_sync(FULLMASK, v1, lane ^ 31);
            float z1 = __shfl_sync(FULLMASK, v0, lane ^ 31);

            float cz0 = iscan(z0, lane);
            float tot = __shfl_sync(FULLMASK, cz0, 31);
            float cz1 = iscan(z1, lane) + tot;
            float q0  = iscan(z0 * z0, lane);
            float qt  = __shfl_sync(FULLMASK, q0, 31);
            float q1  = iscan(z1 * z1, lane) + qt;

            float kAf = (float)(lane + 1), kBf = (float)(lane + 33);
            float rkA = __fdividef(1.0f, kAf), rkB = __fdividef(1.0f, kBf);
            float mzA = cz0 * rkA, mz2A = q0 * rkA;
            float tcA = mzA - sqrtf(fmaxf(mzA * mzA - mz2A + rkA, 0.f));
            float mzB = cz1 * rkB, mz2B = q1 * rkB;
            float tcB = mzB - sqrtf(fmaxf(mzB * mzB - mz2B + rkB, 0.f));

            int k15 = wredsumi((z0 > tcA ? 1 : 0) + (z1 > tcB ? 1 : 0));
            int p15 = k15 - 1;
            float tA = __shfl_sync(FULLMASK, tcA, p15 & 31);
            float tB = __shfl_sync(FULLMASK, tcB, p15 & 31);
            float tau15 = (p15 < 32) ? tA : tB;
            float r0 = fmaxf(vA - tau15, 0.f); float p15A = r0 * r0;
            float r1 = fmaxf(vB - tau15, 0.f); float p15B = r1 * r1;

            float prA, prB;
            if (lowU) {
                float w = uu * 2.0f;
                prA = (1.0f - w) * psA + w * p15A;
                prB = (1.0f - w) * psB + w * p15B;
            } else {
                int ksp = wredsumi(((kAf * z0 > cz0 - 1.0f) ? 1 : 0) + ((kBf * z1 > cz1 - 1.0f) ? 1 : 0));
                int psp = ksp - 1;
                float cA = __shfl_sync(FULLMASK, cz0, psp & 31);
                float cB = __shfl_sync(FULLMASK, cz1, psp & 31);
                float csk = (psp < 32) ? cA : cB;
                float tausp = __fdividef(csk - 1.0f, (float)ksp);
                float pspA = fmaxf(vA - tausp, 0.f);
                float pspB = fmaxf(vB - tausp, 0.f);
                float w = (uu - 0.5f) * 2.0f;
                prA = (1.0f - w) * p15A + w * pspA;
                prB = (1.0f - w) * p15B + w * pspB;
            }
            float selA = (prA > 1e-6f) ? 1.f : 0.f;
            float selB = (prB > 1e-6f) ? 1.f : 0.f;
            float ssum = wredsum(selA + selB) + 1e-9f;
            attA = ((selA / ssum) - prA) + prA; if (!actA) attA = 0.f;
            attB = ((selB / ssum) - prB) + prB; if (!actB) attB = 0.f;
        }

        // ---- stage per-entry data (warp-private; only __syncwarp needed) ----
        sAtt[warp][lane] = attA;  sAtt[warp][lane + 32] = attB;
        sD[warp][lane]   = da;    sD[warp][lane + 32]   = db;
        __syncwarp();

        // ---- aggregate (lane owns columns 4*lane..4*lane+3); 3 lookups -----
        float a0 = sAtt[warp][0];
        float4 acc = make_float4(0.f, 0.f, 0.f, 0.f);
        if (a0 != 0.f) {
            float4 t = T4[nc * 32 + lane];
            acc.x = a0 * t.x; acc.y = a0 * t.y; acc.z = a0 * t.z; acc.w = a0 * t.w;
        }
#pragma unroll 2
        for (int i = 1; i < A; i++) {
            float a = sAtt[warp][i];
            if (a != 0.f) {
                int p = (int)(sD[warp][i] >> 32);
                float4 t0 = T4[(p & 15) * 32 + lane];
                float4 t1 = T4[(16 + ((p >> 4) & 15)) * 32 + lane];
                float4 t2 = T4[(32 + ((p >> 8) & 63)) * 32 + lane];   // VeS = Ve2+Vs
                acc.x += a * (t0.x + t1.x + t2.x);
                acc.y += a * (t0.y + t1.y + t2.y);
                acc.z += a * (t0.z + t1.z + t2.z);
                acc.w += a * (t0.w + t1.w + t2.w);
            }
        }

        // ---- node output: node_fts + agg ----
        float4 nf = __ldg(((const float4*)emb_v) + (2 * nc) * 32 + lane);
        float4 no = make_float4(acc.x + nf.x, acc.y + nf.y, acc.z + nf.z, acc.w + nf.w);
        __stcs(((float4*)out_node) + n * 32 + lane, no);

        // ---- edge outputs: emb_e[ec] + agg, written directly per edge ----
#pragma unroll 2
        for (int i = 1; i < A; i++) {
            unsigned long long d = sD[warp][i];
            int p = (int)(d >> 32);
            int e = (int)(d & 0xffffffffull);
            float4 t = T4[(96 + ((p >> 4) & 15)) * 32 + lane];
            float4 o = make_float4(acc.x + t.x, acc.y + t.y, acc.z + t.z, acc.w + t.w);
            __stcs(((float4*)out_edge) + (size_t)e * 32 + lane, o);
        }

        // ---- rotate prefetched state ----
        n = nn; nc = nc2; deg = deg2; da = da2; db = db2;
    }
}

// ------------------------ host launch ----------------------------------------
extern "C" void kernel_launch(void* const* d_in, const int* in_sizes, int n_in,
                              void* d_out, int out_size) {
    const int*   node_states = (const int*)d_in[0];
    const int*   edge_states = (const int*)d_in[1];
    const float* scalars     = (const float*)d_in[2];
    const int*   src         = (const int*)d_in[3];
    const int*   dst         = (const int*)d_in[4];
    const int*   rev         = (const int*)d_in[5];
    const int*   slot        = (const int*)d_in[6];
    // d_in[7] = self_loop_idx (identity, unused)

    int w = 8;
    if (w < n_in && in_sizes[w] == 1) w++;   // skip max_deg scalar if present
    const float* emb_v = (const float*)d_in[w + 0];
    const float* emb_b = (const float*)d_in[w + 1];
    const float* emb_e = (const float*)d_in[w + 2];
    const float* emb_s = (const float*)d_in[w + 3];
    const float* Wq    = (const float*)d_in[w + 4];
    const float* Wk    = (const float*)d_in[w + 5];
    const float* Wv    = (const float*)d_in[w + 6];
    const float* Wek   = (const float*)d_in[w + 7];
    const float* Wev   = (const float*)d_in[w + 8];
    const float* Wcf   = (const float*)d_in[w + 9];
    const float* gW1   = (const float*)d_in[w + 10];
    const float* gb1   = (const float*)d_in[w + 11];
    const float* gW2   = (const float*)d_in[w + 12];
    const float* gb2   = (const float*)d_in[w + 13];

    float* out_node = (float*)d_out;
    float* out_edge = (float*)d_out + (size_t)N_NODES * 128;

    static int smem_configured = 0;
    if (!smem_configured) {
        cudaFuncSetAttribute(k_attn, cudaFuncAttributeMaxDynamicSharedMemorySize, STAB_BYTES);
        smem_configured = 1;
    }

    k_init<<<(N_EDGES + 255) / 256, 256>>>(node_states, edge_states);
    k_pre<<<12, 128>>>(emb_v, emb_b, emb_e, emb_s, Wq, Wk, Wv, Wek,
                       gW1, gb1, Wcf, Wev, gW2, gb2);
    k_pack<<<(N_EDGES + 255) / 256, 256>>>(src, dst, rev, slot, scalars);
    k_attn<<<ATTN_BLOCKS, 512, STAB_BYTES>>>(emb_v, emb_e, out_node, out_edge);
}